// round 1
// baseline (speedup 1.0000x reference)
#include <cuda_runtime.h>
#include <math.h>

// Shapes
#define M_ROWS 4096   // B*T
#define C_DIM  1024
#define FF_DIM 4096
#define A_DIM  64
#define T_LEN  1024
#define NHEAD  16
#define HDIM   64

// ---------------- scratch (device globals; no allocs allowed) ----------------
__device__ float g_h     [M_ROWS * C_DIM];   // ln1(x)
__device__ float g_q     [M_ROWS * C_DIM];
__device__ float g_k     [M_ROWS * C_DIM];
__device__ float g_v     [M_ROWS * C_DIM];
__device__ float g_y     [M_ROWS * C_DIM];   // attention output (pre-Wo)
__device__ float g_hidden[M_ROWS * C_DIM];   // x + attn_out
__device__ float g_m     [M_ROWS * C_DIM];   // ln2(hidden)
__device__ float g_ff    [M_ROWS * FF_DIM];  // gelu(m@w1+b1)
__device__ float g_mlp   [M_ROWS * C_DIM];   // ff@w2+b2
__device__ float g_n3    [M_ROWS * C_DIM];   // ln3(x)
__device__ float g_ad1   [M_ROWS * A_DIM];   // relu(n3@wd+bd)
__device__ float g_a     [M_ROWS * C_DIM];   // adapter out

// ---------------- LayerNorm: one block per row, C=1024 ----------------
__global__ __launch_bounds__(256) void ln_kernel(const float* __restrict__ x,
                                                 const float* __restrict__ g,
                                                 const float* __restrict__ b,
                                                 float* __restrict__ out) {
    __shared__ float red[256];
    const int row = blockIdx.x;
    const int tid = threadIdx.x;
    const float* xr = x + (size_t)row * C_DIM;

    float v[4];
    float s = 0.f;
#pragma unroll
    for (int i = 0; i < 4; i++) { v[i] = xr[tid + i * 256]; s += v[i]; }
    red[tid] = s; __syncthreads();
    for (int off = 128; off > 0; off >>= 1) {
        if (tid < off) red[tid] += red[tid + off];
        __syncthreads();
    }
    const float mean = red[0] * (1.0f / 1024.0f);
    __syncthreads();

    float sq = 0.f;
#pragma unroll
    for (int i = 0; i < 4; i++) { float d = v[i] - mean; sq += d * d; }
    red[tid] = sq; __syncthreads();
    for (int off = 128; off > 0; off >>= 1) {
        if (tid < off) red[tid] += red[tid + off];
        __syncthreads();
    }
    const float inv = rsqrtf(red[0] * (1.0f / 1024.0f) + 1e-5f);

    float* orow = out + (size_t)row * C_DIM;
#pragma unroll
    for (int i = 0; i < 4; i++) {
        int col = tid + i * 256;
        orow[col] = (v[i] - mean) * inv * g[col] + b[col];
    }
}

// ---------------- SGEMM: C[M,N] = act(A[M,K] @ B[K,N] + bias) (+ res) --------
__device__ __forceinline__ float gelu_exact(float x) {
    return 0.5f * x * (1.0f + erff(x * 0.7071067811865476f));
}

// ACT: 0 = none, 1 = gelu(exact), 2 = relu.  RES: add res[M,N] in epilogue.
template <int ACT, bool RES>
__global__ __launch_bounds__(256) void sgemm_kernel(
    const float* __restrict__ A, const float* __restrict__ B,
    const float* __restrict__ bias, const float* __restrict__ res,
    float* __restrict__ C, int M, int N, int K)
{
    __shared__ float As[16][64];  // [k][m]
    __shared__ float Bs[16][64];  // [k][n]

    const int tid = threadIdx.x;
    const int m0 = blockIdx.y * 64;
    const int n0 = blockIdx.x * 64;

    const int aRow = tid >> 2;          // 0..63
    const int aK   = (tid & 3) * 4;     // 0,4,8,12
    const int bRow = tid >> 4;          // 0..15
    const int bC   = (tid & 15) * 4;    // 0..60
    const int rm   = (tid >> 4) * 4;    // 0..60
    const int cn   = (tid & 15) * 4;    // 0..60

    float acc[4][4];
#pragma unroll
    for (int i = 0; i < 4; i++)
#pragma unroll
        for (int j = 0; j < 4; j++) acc[i][j] = 0.f;

    for (int kt = 0; kt < K; kt += 16) {
        const float4 a4 = *(const float4*)(A + (size_t)(m0 + aRow) * K + kt + aK);
        const float4 b4 = *(const float4*)(B + (size_t)(kt + bRow) * N + n0 + bC);
        __syncthreads();
        As[aK + 0][aRow] = a4.x;
        As[aK + 1][aRow] = a4.y;
        As[aK + 2][aRow] = a4.z;
        As[aK + 3][aRow] = a4.w;
        *(float4*)&Bs[bRow][bC] = b4;
        __syncthreads();
#pragma unroll
        for (int kk = 0; kk < 16; kk++) {
            const float4 av = *(const float4*)&As[kk][rm];
            const float4 bv = *(const float4*)&Bs[kk][cn];
            const float a_[4] = {av.x, av.y, av.z, av.w};
            const float b_[4] = {bv.x, bv.y, bv.z, bv.w};
#pragma unroll
            for (int i = 0; i < 4; i++)
#pragma unroll
                for (int j = 0; j < 4; j++) acc[i][j] += a_[i] * b_[j];
        }
    }

#pragma unroll
    for (int i = 0; i < 4; i++) {
        const int row = m0 + rm + i;
        float4 o;
        float cvals[4];
#pragma unroll
        for (int j = 0; j < 4; j++) {
            const int col = n0 + cn + j;
            float c = acc[i][j] + bias[col];
            if (ACT == 1) c = gelu_exact(c);
            else if (ACT == 2) c = fmaxf(c, 0.f);
            if (RES) c += res[(size_t)row * N + col];
            cvals[j] = c;
        }
        o.x = cvals[0]; o.y = cvals[1]; o.z = cvals[2]; o.w = cvals[3];
        *(float4*)(C + (size_t)row * N + n0 + cn) = o;
    }
}

// ---------------- Flash attention: causal, per (b,h), 64-query tiles ---------
// blockDim = 64 (each thread owns one query row of the tile).
__global__ __launch_bounds__(64) void attn_kernel(const float* __restrict__ q,
                                                  const float* __restrict__ k,
                                                  const float* __restrict__ v,
                                                  float* __restrict__ y) {
    __shared__ float Qt[64][64];  // swizzled [d][(qrow+d)&63]
    __shared__ float Ks[64][64];  // [krow][d]
    __shared__ float Vs[64][64];  // [krow][d]

    const int b  = blockIdx.x >> 4;
    const int h  = blockIdx.x & 15;
    const int qb = blockIdx.y;
    const int q0 = qb * 64;
    const int tid = threadIdx.x;  // query row within tile; also d-index for loads

    const float* qp = q + (size_t)b * T_LEN * C_DIM + h * HDIM;
    const float* kp = k + (size_t)b * T_LEN * C_DIM + h * HDIM;
    const float* vp = v + (size_t)b * T_LEN * C_DIM + h * HDIM;

    // Load Q tile, d-major, swizzled to keep both STS and LDS conflict-free.
    for (int r = 0; r < 64; r++)
        Qt[tid][(r + tid) & 63] = qp[(size_t)(q0 + r) * C_DIM + tid];

    float acc[64];
#pragma unroll
    for (int d = 0; d < 64; d++) acc[d] = 0.f;
    float mi = -1e30f, li = 0.f;

    for (int kb = 0; kb <= qb; kb++) {
        __syncthreads();
        for (int r = 0; r < 64; r++) {
            Ks[r][tid] = kp[(size_t)(kb * 64 + r) * C_DIM + tid];
            Vs[r][tid] = vp[(size_t)(kb * 64 + r) * C_DIM + tid];
        }
        __syncthreads();

        float s[64];
#pragma unroll
        for (int j = 0; j < 64; j++) s[j] = 0.f;
        for (int d = 0; d < 64; d++) {
            const float qd = Qt[d][(tid + d) & 63];
#pragma unroll
            for (int j = 0; j < 64; j++) s[j] += qd * Ks[j][d];
        }

        float mb = -1e30f;
#pragma unroll
        for (int j = 0; j < 64; j++) {
            s[j] *= 0.125f;  // 1/sqrt(64)
            if (kb == qb && j > tid) s[j] = -1e30f;  // causal mask (diag block)
            mb = fmaxf(mb, s[j]);
        }
        const float m_new = fmaxf(mi, mb);
        const float alpha = expf(mi - m_new);
        li *= alpha;
#pragma unroll
        for (int d = 0; d < 64; d++) acc[d] *= alpha;
#pragma unroll
        for (int j = 0; j < 64; j++) {
            s[j] = expf(s[j] - m_new);
            li += s[j];
        }
#pragma unroll
        for (int j = 0; j < 64; j++) {
#pragma unroll
            for (int d = 0; d < 64; d++) acc[d] += s[j] * Vs[j][d];
        }
        mi = m_new;
    }

    // Transpose through smem (reuse Ks) for coalesced output stores.
    const float inv = 1.f / li;
    __syncthreads();
#pragma unroll
    for (int d = 0; d < 64; d++) Ks[tid][(d + tid) & 63] = acc[d] * inv;
    __syncthreads();
    float* yp = y + (size_t)b * T_LEN * C_DIM + h * HDIM;
    for (int r = 0; r < 64; r++)
        yp[(size_t)(q0 + r) * C_DIM + tid] = Ks[r][(tid + r) & 63];
}

// ---------------- final combine: out = 2*hidden + mlp + adapter --------------
__global__ void combine_kernel(const float* __restrict__ hidden,
                               const float* __restrict__ mlp,
                               const float* __restrict__ a,
                               float* __restrict__ out, int n) {
    int i = blockIdx.x * blockDim.x + threadIdx.x;
    if (i < n) out[i] = 2.f * hidden[i] + mlp[i] + a[i];
}

// -----------------------------------------------------------------------------
extern "C" void kernel_launch(void* const* d_in, const int* in_sizes, int n_in,
                              void* d_out, int out_size) {
    const float* x     = (const float*)d_in[0];
    const float* ln1_g = (const float*)d_in[1];
    const float* ln1_b = (const float*)d_in[2];
    const float* ln2_g = (const float*)d_in[3];
    const float* ln2_b = (const float*)d_in[4];
    const float* ln3_g = (const float*)d_in[5];
    const float* ln3_b = (const float*)d_in[6];
    const float* wq = (const float*)d_in[7];   const float* bq = (const float*)d_in[8];
    const float* wk = (const float*)d_in[9];   const float* bk = (const float*)d_in[10];
    const float* wv = (const float*)d_in[11];  const float* bv = (const float*)d_in[12];
    const float* wo = (const float*)d_in[13];  const float* bo = (const float*)d_in[14];
    const float* w1 = (const float*)d_in[15];  const float* b1 = (const float*)d_in[16];
    const float* w2 = (const float*)d_in[17];  const float* b2 = (const float*)d_in[18];
    const float* wd = (const float*)d_in[19];  const float* bd = (const float*)d_in[20];
    const float* wu = (const float*)d_in[21];  const float* bu = (const float*)d_in[22];
    float* out = (float*)d_out;

    float *h, *q, *k, *v, *y, *hidden, *m, *ff, *mlp, *n3, *ad1, *a;
    cudaGetSymbolAddress((void**)&h,      g_h);
    cudaGetSymbolAddress((void**)&q,      g_q);
    cudaGetSymbolAddress((void**)&k,      g_k);
    cudaGetSymbolAddress((void**)&v,      g_v);
    cudaGetSymbolAddress((void**)&y,      g_y);
    cudaGetSymbolAddress((void**)&hidden, g_hidden);
    cudaGetSymbolAddress((void**)&m,      g_m);
    cudaGetSymbolAddress((void**)&ff,     g_ff);
    cudaGetSymbolAddress((void**)&mlp,    g_mlp);
    cudaGetSymbolAddress((void**)&n3,     g_n3);
    cudaGetSymbolAddress((void**)&ad1,    g_ad1);
    cudaGetSymbolAddress((void**)&a,      g_a);

    // LN1(x), LN3(x)
    ln_kernel<<<M_ROWS, 256>>>(x, ln1_g, ln1_b, h);
    ln_kernel<<<M_ROWS, 256>>>(x, ln3_g, ln3_b, n3);

    // QKV projections
    dim3 gCC(C_DIM / 64, M_ROWS / 64);
    sgemm_kernel<0, false><<<gCC, 256>>>(h, wq, bq, nullptr, q, M_ROWS, C_DIM, C_DIM);
    sgemm_kernel<0, false><<<gCC, 256>>>(h, wk, bk, nullptr, k, M_ROWS, C_DIM, C_DIM);
    sgemm_kernel<0, false><<<gCC, 256>>>(h, wv, bv, nullptr, v, M_ROWS, C_DIM, C_DIM);

    // Causal attention
    attn_kernel<<<dim3(4 * NHEAD, T_LEN / 64), 64>>>(q, k, v, y);

    // Output projection + residual -> hidden
    sgemm_kernel<0, true><<<gCC, 256>>>(y, wo, bo, x, hidden, M_ROWS, C_DIM, C_DIM);

    // MLP on ln2(hidden)
    ln_kernel<<<M_ROWS, 256>>>(hidden, ln2_g, ln2_b, m);
    dim3 gCF(FF_DIM / 64, M_ROWS / 64);
    sgemm_kernel<1, false><<<gCF, 256>>>(m, w1, b1, nullptr, ff, M_ROWS, FF_DIM, C_DIM);
    sgemm_kernel<0, false><<<gCC, 256>>>(ff, w2, b2, nullptr, mlp, M_ROWS, C_DIM, FF_DIM);

    // Adapter on ln3(x)
    dim3 gCA(A_DIM / 64, M_ROWS / 64);
    sgemm_kernel<2, false><<<gCA, 256>>>(n3, wd, bd, nullptr, ad1, M_ROWS, A_DIM, C_DIM);
    sgemm_kernel<0, false><<<gCC, 256>>>(ad1, wu, bu, nullptr, a, M_ROWS, C_DIM, A_DIM);

    // out = 2*hidden + mlp + adapter
    const int n = M_ROWS * C_DIM;
    combine_kernel<<<(n + 255) / 256, 256>>>(hidden, mlp, a, out, n);
}

// round 3
// speedup vs baseline: 2.4151x; 2.4151x over previous
#include <cuda_runtime.h>
#include <math.h>
#include <stdint.h>

// Shapes
#define M_ROWS 4096   // B*T
#define C_DIM  1024
#define FF_DIM 4096
#define A_DIM  64
#define T_LEN  1024
#define NHEAD  16
#define HDIM   64

// ---------------- scratch (device globals; no allocs allowed) ----------------
__device__ float g_h     [M_ROWS * C_DIM];
__device__ float g_q     [M_ROWS * C_DIM];
__device__ float g_k     [M_ROWS * C_DIM];
__device__ float g_v     [M_ROWS * C_DIM];
__device__ float g_y     [M_ROWS * C_DIM];
__device__ float g_hidden[M_ROWS * C_DIM];
__device__ float g_m     [M_ROWS * C_DIM];
__device__ float g_ff    [M_ROWS * FF_DIM];
__device__ float g_mlp   [M_ROWS * C_DIM];
__device__ float g_n3    [M_ROWS * C_DIM];
__device__ float g_ad1   [M_ROWS * A_DIM];
__device__ float g_a     [M_ROWS * C_DIM];

// ======================= helpers ==============================================
__device__ __forceinline__ uint32_t s2u(const void* p) {
    uint32_t a;
    asm("{ .reg .u64 t; cvta.to.shared.u64 t, %1; cvt.u32.u64 %0, t; }"
        : "=r"(a) : "l"(p));
    return a;
}
__device__ __forceinline__ void cp16(uint32_t dst, const void* src) {
    asm volatile("cp.async.cg.shared.global [%0], [%1], 16;"
                 :: "r"(dst), "l"(src) : "memory");
}
__device__ __forceinline__ uint32_t f2tf32(float x) {
    uint32_t r;
    asm("cvt.rna.tf32.f32 %0, %1;" : "=r"(r) : "f"(x));
    return r;
}
__device__ __forceinline__ void mma_tf32(float* c, const uint32_t* a, const uint32_t* b) {
    asm volatile(
        "mma.sync.aligned.m16n8k8.row.col.f32.tf32.tf32.f32 "
        "{%0,%1,%2,%3}, {%4,%5,%6,%7}, {%8,%9}, {%0,%1,%2,%3};"
        : "+f"(c[0]), "+f"(c[1]), "+f"(c[2]), "+f"(c[3])
        : "r"(a[0]), "r"(a[1]), "r"(a[2]), "r"(a[3]), "r"(b[0]), "r"(b[1]));
}
__device__ __forceinline__ float gelu_exact(float x) {
    return 0.5f * x * (1.0f + erff(x * 0.7071067811865476f));
}

// =========================== tf32 mma.sync GEMM ===============================
// C[M,N] = act(A[M,K] @ W[K,N] + bias) (+res). 128x128 CTA tile, K staged by 32.
#define BM 128
#define BN 128
#define BK 32
#define A_LD 36                 // padded floats per A row  (bank-safe)
#define B_LD 132                // padded floats per B k-row
#define A_STAGE_F (BM * A_LD)   // 4608 floats = 18432 B
#define B_STAGE_F (BK * B_LD)   // 4224 floats = 16896 B
#define STAGE_F   (A_STAGE_F + B_STAGE_F)
#define GEMM_SMEM (2 * STAGE_F * 4)   // 70656 B

// ACT: 0 none, 1 gelu(exact), 2 relu.  RES: add res in epilogue.
template <int ACT, bool RES>
__global__ __launch_bounds__(256) void tc_gemm(
    const float* __restrict__ A, const float* __restrict__ W,
    const float* __restrict__ bias, const float* __restrict__ res,
    float* __restrict__ C, int M, int N, int K)
{
    extern __shared__ float smem[];
    const int tid  = threadIdx.x;
    const int wid  = tid >> 5;
    const int lane = tid & 31;
    const int g    = lane >> 2;      // group 0..7
    const int tig  = lane & 3;       // thread-in-group
    const int wm   = wid >> 2;       // 0..1 (64 rows each)
    const int wn   = wid & 3;        // 0..3 (32 cols each)
    const int m0 = blockIdx.y * BM;
    const int n0 = blockIdx.x * BN;

    const uint32_t sb = s2u(smem);

    // --- async stage loader: A[128][36], B[32][132] ---
    auto load_stage = [&](int s, int b) {
        const uint32_t abase = sb + (uint32_t)(b * STAGE_F) * 4;
        const uint32_t bbase = abase + A_STAGE_F * 4;
        const float* Ag = A + (size_t)m0 * K + s * BK;
        const float* Wg = W + (size_t)(s * BK) * N + n0;
#pragma unroll
        for (int i = 0; i < 4; i++) {           // A: 128 rows x 8 chunks of 16B
            int c = tid + i * 256;
            int row = c >> 3, k4 = c & 7;
            cp16(abase + row * (A_LD * 4) + k4 * 16,
                 Ag + (size_t)row * K + k4 * 4);
        }
#pragma unroll
        for (int i = 0; i < 4; i++) {           // B: 32 k-rows x 32 chunks of 16B
            int c = tid + i * 256;
            int kr = c >> 5, n4 = c & 31;
            cp16(bbase + kr * (B_LD * 4) + n4 * 16,
                 Wg + (size_t)kr * N + n4 * 4);
        }
        asm volatile("cp.async.commit_group;" ::: "memory");
    };

    float acc[4][4][4];
#pragma unroll
    for (int mi = 0; mi < 4; mi++)
#pragma unroll
        for (int ni = 0; ni < 4; ni++)
#pragma unroll
            for (int t = 0; t < 4; t++) acc[mi][ni][t] = 0.f;

    const int NS = K / BK;
    load_stage(0, 0);

    for (int s = 0; s < NS; s++) {
        const int buf = s & 1;
        if (s + 1 < NS) {
            load_stage(s + 1, buf ^ 1);
            asm volatile("cp.async.wait_group 1;" ::: "memory");
        } else {
            asm volatile("cp.async.wait_group 0;" ::: "memory");
        }
        __syncthreads();

        const float* As = smem + buf * STAGE_F;
        const float* Bs = As + A_STAGE_F;

#pragma unroll
        for (int ks = 0; ks < 4; ks++) {
            uint32_t afr[4][4];
#pragma unroll
            for (int mi = 0; mi < 4; mi++) {
                const float* p = As + (wm * 64 + mi * 16 + g) * A_LD + ks * 8 + tig;
                afr[mi][0] = f2tf32(p[0]);
                afr[mi][1] = f2tf32(p[8 * A_LD]);
                afr[mi][2] = f2tf32(p[4]);
                afr[mi][3] = f2tf32(p[8 * A_LD + 4]);
            }
            uint32_t bfr[4][2];
#pragma unroll
            for (int ni = 0; ni < 4; ni++) {
                const float* p = Bs + (ks * 8 + tig) * B_LD + wn * 32 + ni * 8 + g;
                bfr[ni][0] = f2tf32(p[0]);
                bfr[ni][1] = f2tf32(p[4 * B_LD]);
            }
#pragma unroll
            for (int mi = 0; mi < 4; mi++)
#pragma unroll
                for (int ni = 0; ni < 4; ni++)
                    mma_tf32(acc[mi][ni], afr[mi], bfr[ni]);
        }
        __syncthreads();
    }

    // --- epilogue ---
#pragma unroll
    for (int mi = 0; mi < 4; mi++) {
        const int r0 = m0 + wm * 64 + mi * 16 + g;
#pragma unroll
        for (int ni = 0; ni < 4; ni++) {
            const int col = n0 + wn * 32 + ni * 8 + tig * 2;
            const float bx = bias[col], by = bias[col + 1];
#pragma unroll
            for (int h = 0; h < 2; h++) {       // h=0: row r0, h=1: row r0+8
                const int row = r0 + h * 8;
                float cx = acc[mi][ni][h * 2 + 0] + bx;
                float cy = acc[mi][ni][h * 2 + 1] + by;
                if (ACT == 1) { cx = gelu_exact(cx); cy = gelu_exact(cy); }
                else if (ACT == 2) { cx = fmaxf(cx, 0.f); cy = fmaxf(cy, 0.f); }
                if (RES) {
                    cx += res[(size_t)row * N + col];
                    cy += res[(size_t)row * N + col + 1];
                }
                float2 o = make_float2(cx, cy);
                *(float2*)(C + (size_t)row * N + col) = o;
            }
        }
    }
}

// ---------------- LayerNorm: one block per row, C=1024 ----------------
__global__ __launch_bounds__(256) void ln_kernel(const float* __restrict__ x,
                                                 const float* __restrict__ g,
                                                 const float* __restrict__ b,
                                                 float* __restrict__ out) {
    __shared__ float red[256];
    const int row = blockIdx.x;
    const int tid = threadIdx.x;
    const float* xr = x + (size_t)row * C_DIM;

    float v[4];
    float s = 0.f;
#pragma unroll
    for (int i = 0; i < 4; i++) { v[i] = xr[tid + i * 256]; s += v[i]; }
    red[tid] = s; __syncthreads();
    for (int off = 128; off > 0; off >>= 1) {
        if (tid < off) red[tid] += red[tid + off];
        __syncthreads();
    }
    const float mean = red[0] * (1.0f / 1024.0f);
    __syncthreads();

    float sq = 0.f;
#pragma unroll
    for (int i = 0; i < 4; i++) { float d = v[i] - mean; sq += d * d; }
    red[tid] = sq; __syncthreads();
    for (int off = 128; off > 0; off >>= 1) {
        if (tid < off) red[tid] += red[tid + off];
        __syncthreads();
    }
    const float inv = rsqrtf(red[0] * (1.0f / 1024.0f) + 1e-5f);

    float* orow = out + (size_t)row * C_DIM;
#pragma unroll
    for (int i = 0; i < 4; i++) {
        int col = tid + i * 256;
        orow[col] = (v[i] - mean) * inv * g[col] + b[col];
    }
}

// ------------- SIMT SGEMM (adapter path only) --------------------------------
template <int ACT, bool RES>
__global__ __launch_bounds__(256) void sgemm_kernel(
    const float* __restrict__ A, const float* __restrict__ B,
    const float* __restrict__ bias, const float* __restrict__ res,
    float* __restrict__ C, int M, int N, int K)
{
    __shared__ float As[16][64];
    __shared__ float Bs[16][64];

    const int tid = threadIdx.x;
    const int m0 = blockIdx.y * 64;
    const int n0 = blockIdx.x * 64;

    const int aRow = tid >> 2;
    const int aK   = (tid & 3) * 4;
    const int bRow = tid >> 4;
    const int bC   = (tid & 15) * 4;
    const int rm   = (tid >> 4) * 4;
    const int cn   = (tid & 15) * 4;

    float acc[4][4];
#pragma unroll
    for (int i = 0; i < 4; i++)
#pragma unroll
        for (int j = 0; j < 4; j++) acc[i][j] = 0.f;

    for (int kt = 0; kt < K; kt += 16) {
        const float4 a4 = *(const float4*)(A + (size_t)(m0 + aRow) * K + kt + aK);
        const float4 b4 = *(const float4*)(B + (size_t)(kt + bRow) * N + n0 + bC);
        __syncthreads();
        As[aK + 0][aRow] = a4.x;
        As[aK + 1][aRow] = a4.y;
        As[aK + 2][aRow] = a4.z;
        As[aK + 3][aRow] = a4.w;
        *(float4*)&Bs[bRow][bC] = b4;
        __syncthreads();
#pragma unroll
        for (int kk = 0; kk < 16; kk++) {
            const float4 av = *(const float4*)&As[kk][rm];
            const float4 bv = *(const float4*)&Bs[kk][cn];
            const float a_[4] = {av.x, av.y, av.z, av.w};
            const float b_[4] = {bv.x, bv.y, bv.z, bv.w};
#pragma unroll
            for (int i = 0; i < 4; i++)
#pragma unroll
                for (int j = 0; j < 4; j++) acc[i][j] += a_[i] * b_[j];
        }
    }

#pragma unroll
    for (int i = 0; i < 4; i++) {
        const int row = m0 + rm + i;
        float4 o;
        float cvals[4];
#pragma unroll
        for (int j = 0; j < 4; j++) {
            const int col = n0 + cn + j;
            float c = acc[i][j] + bias[col];
            if (ACT == 1) c = gelu_exact(c);
            else if (ACT == 2) c = fmaxf(c, 0.f);
            if (RES) c += res[(size_t)row * N + col];
            cvals[j] = c;
        }
        o.x = cvals[0]; o.y = cvals[1]; o.z = cvals[2]; o.w = cvals[3];
        *(float4*)(C + (size_t)row * N + n0 + cn) = o;
    }
}

// ---------------- Flash attention: causal, per (b,h), 64-query tiles ---------
__global__ __launch_bounds__(64) void attn_kernel(const float* __restrict__ q,
                                                  const float* __restrict__ k,
                                                  const float* __restrict__ v,
                                                  float* __restrict__ y) {
    __shared__ float Qt[64][64];
    __shared__ float Ks[64][64];
    __shared__ float Vs[64][64];

    const int b  = blockIdx.x >> 4;
    const int h  = blockIdx.x & 15;
    const int qb = blockIdx.y;
    const int q0 = qb * 64;
    const int tid = threadIdx.x;

    const float* qp = q + (size_t)b * T_LEN * C_DIM + h * HDIM;
    const float* kp = k + (size_t)b * T_LEN * C_DIM + h * HDIM;
    const float* vp = v + (size_t)b * T_LEN * C_DIM + h * HDIM;

    for (int r = 0; r < 64; r++)
        Qt[tid][(r + tid) & 63] = qp[(size_t)(q0 + r) * C_DIM + tid];

    float acc[64];
#pragma unroll
    for (int d = 0; d < 64; d++) acc[d] = 0.f;
    float mi = -1e30f, li = 0.f;

    for (int kb = 0; kb <= qb; kb++) {
        __syncthreads();
        for (int r = 0; r < 64; r++) {
            Ks[r][tid] = kp[(size_t)(kb * 64 + r) * C_DIM + tid];
            Vs[r][tid] = vp[(size_t)(kb * 64 + r) * C_DIM + tid];
        }
        __syncthreads();

        float s[64];
#pragma unroll
        for (int j = 0; j < 64; j++) s[j] = 0.f;
        for (int d = 0; d < 64; d++) {
            const float qd = Qt[d][(tid + d) & 63];
#pragma unroll
            for (int j = 0; j < 64; j++) s[j] += qd * Ks[j][d];
        }

        float mb = -1e30f;
#pragma unroll
        for (int j = 0; j < 64; j++) {
            s[j] *= 0.125f;
            if (kb == qb && j > tid) s[j] = -1e30f;
            mb = fmaxf(mb, s[j]);
        }
        const float m_new = fmaxf(mi, mb);
        const float alpha = expf(mi - m_new);
        li *= alpha;
#pragma unroll
        for (int d = 0; d < 64; d++) acc[d] *= alpha;
#pragma unroll
        for (int j = 0; j < 64; j++) {
            s[j] = expf(s[j] - m_new);
            li += s[j];
        }
#pragma unroll
        for (int j = 0; j < 64; j++) {
#pragma unroll
            for (int d = 0; d < 64; d++) acc[d] += s[j] * Vs[j][d];
        }
        mi = m_new;
    }

    const float inv = 1.f / li;
    __syncthreads();
#pragma unroll
    for (int d = 0; d < 64; d++) Ks[tid][(d + tid) & 63] = acc[d] * inv;
    __syncthreads();
    float* yp = y + (size_t)b * T_LEN * C_DIM + h * HDIM;
    for (int r = 0; r < 64; r++)
        yp[(size_t)(q0 + r) * C_DIM + tid] = Ks[r][(tid + r) & 63];
}

// ---------------- final combine: out = 2*hidden + mlp + adapter --------------
__global__ void combine_kernel(const float* __restrict__ hidden,
                               const float* __restrict__ mlp,
                               const float* __restrict__ a,
                               float* __restrict__ out, int n) {
    int i = blockIdx.x * blockDim.x + threadIdx.x;
    if (i < n) out[i] = 2.f * hidden[i] + mlp[i] + a[i];
}

// -----------------------------------------------------------------------------
extern "C" void kernel_launch(void* const* d_in, const int* in_sizes, int n_in,
                              void* d_out, int out_size) {
    const float* x     = (const float*)d_in[0];
    const float* ln1_g = (const float*)d_in[1];
    const float* ln1_b = (const float*)d_in[2];
    const float* ln2_g = (const float*)d_in[3];
    const float* ln2_b = (const float*)d_in[4];
    const float* ln3_g = (const float*)d_in[5];
    const float* ln3_b = (const float*)d_in[6];
    const float* wq = (const float*)d_in[7];   const float* bq = (const float*)d_in[8];
    const float* wk = (const float*)d_in[9];   const float* bk = (const float*)d_in[10];
    const float* wv = (const float*)d_in[11];  const float* bv = (const float*)d_in[12];
    const float* wo = (const float*)d_in[13];  const float* bo = (const float*)d_in[14];
    const float* w1 = (const float*)d_in[15];  const float* b1 = (const float*)d_in[16];
    const float* w2 = (const float*)d_in[17];  const float* b2 = (const float*)d_in[18];
    const float* wd = (const float*)d_in[19];  const float* bd = (const float*)d_in[20];
    const float* wu = (const float*)d_in[21];  const float* bu = (const float*)d_in[22];
    float* out = (float*)d_out;

    float *h, *q, *k, *v, *y, *hidden, *m, *ff, *mlp, *n3, *ad1, *a;
    cudaGetSymbolAddress((void**)&h,      g_h);
    cudaGetSymbolAddress((void**)&q,      g_q);
    cudaGetSymbolAddress((void**)&k,      g_k);
    cudaGetSymbolAddress((void**)&v,      g_v);
    cudaGetSymbolAddress((void**)&y,      g_y);
    cudaGetSymbolAddress((void**)&hidden, g_hidden);
    cudaGetSymbolAddress((void**)&m,      g_m);
    cudaGetSymbolAddress((void**)&ff,     g_ff);
    cudaGetSymbolAddress((void**)&mlp,    g_mlp);
    cudaGetSymbolAddress((void**)&n3,     g_n3);
    cudaGetSymbolAddress((void**)&ad1,    g_ad1);
    cudaGetSymbolAddress((void**)&a,      g_a);

    cudaFuncSetAttribute(tc_gemm<0, false>, cudaFuncAttributeMaxDynamicSharedMemorySize, GEMM_SMEM);
    cudaFuncSetAttribute(tc_gemm<0, true>,  cudaFuncAttributeMaxDynamicSharedMemorySize, GEMM_SMEM);
    cudaFuncSetAttribute(tc_gemm<1, false>, cudaFuncAttributeMaxDynamicSharedMemorySize, GEMM_SMEM);

    // LN1(x), LN3(x)
    ln_kernel<<<M_ROWS, 256>>>(x, ln1_g, ln1_b, h);
    ln_kernel<<<M_ROWS, 256>>>(x, ln3_g, ln3_b, n3);

    // QKV projections (tensor core tf32, mma.sync)
    dim3 gCC(C_DIM / BN, M_ROWS / BM);   // (8, 32)
    tc_gemm<0, false><<<gCC, 256, GEMM_SMEM>>>(h, wq, bq, nullptr, q, M_ROWS, C_DIM, C_DIM);
    tc_gemm<0, false><<<gCC, 256, GEMM_SMEM>>>(h, wk, bk, nullptr, k, M_ROWS, C_DIM, C_DIM);
    tc_gemm<0, false><<<gCC, 256, GEMM_SMEM>>>(h, wv, bv, nullptr, v, M_ROWS, C_DIM, C_DIM);

    // Causal attention
    attn_kernel<<<dim3(4 * NHEAD, T_LEN / 64), 64>>>(q, k, v, y);

    // Output projection + residual -> hidden
    tc_gemm<0, true><<<gCC, 256, GEMM_SMEM>>>(y, wo, bo, x, hidden, M_ROWS, C_DIM, C_DIM);

    // MLP on ln2(hidden)
    ln_kernel<<<M_ROWS, 256>>>(hidden, ln2_g, ln2_b, m);
    dim3 gCF(FF_DIM / BN, M_ROWS / BM);  // (32, 32)
    tc_gemm<1, false><<<gCF, 256, GEMM_SMEM>>>(m, w1, b1, nullptr, ff, M_ROWS, FF_DIM, C_DIM);
    tc_gemm<0, false><<<gCC, 256, GEMM_SMEM>>>(ff, w2, b2, nullptr, mlp, M_ROWS, C_DIM, FF_DIM);

    // Adapter on ln3(x) (small; SIMT fp32)
    dim3 gCA(A_DIM / 64, M_ROWS / 64);
    sgemm_kernel<2, false><<<gCA, 256>>>(n3, wd, bd, nullptr, ad1, M_ROWS, A_DIM, C_DIM);
    dim3 gAU(C_DIM / 64, M_ROWS / 64);
    sgemm_kernel<0, false><<<gAU, 256>>>(ad1, wu, bu, nullptr, a, M_ROWS, C_DIM, A_DIM);

    // out = 2*hidden + mlp + adapter
    const int n = M_ROWS * C_DIM;
    combine_kernel<<<(n + 255) / 256, 256>>>(hidden, mlp, a, out, n);
}

// round 4
// speedup vs baseline: 3.0811x; 1.2758x over previous
#include <cuda_runtime.h>
#include <math.h>
#include <stdint.h>

// Shapes
#define M_ROWS 4096   // B*T
#define C_DIM  1024
#define FF_DIM 4096
#define A_DIM  64
#define T_LEN  1024
#define NHEAD  16
#define HDIM   64

// ---------------- scratch (device globals; no allocs allowed) ----------------
__device__ float g_h     [M_ROWS * C_DIM];
__device__ float g_q     [M_ROWS * C_DIM];
__device__ float g_k     [M_ROWS * C_DIM];
__device__ float g_v     [M_ROWS * C_DIM];
__device__ float g_y     [M_ROWS * C_DIM];
__device__ float g_hidden[M_ROWS * C_DIM];
__device__ float g_m     [M_ROWS * C_DIM];
__device__ float g_ff    [M_ROWS * FF_DIM];
__device__ float g_mlp   [M_ROWS * C_DIM];
__device__ float g_n3    [M_ROWS * C_DIM];
__device__ float g_ad1   [M_ROWS * A_DIM];
__device__ float g_a     [M_ROWS * C_DIM];

// ======================= helpers ==============================================
__device__ __forceinline__ void cp16(uint32_t dst, const void* src) {
    asm volatile("cp.async.cg.shared.global [%0], [%1], 16;"
                 :: "r"(dst), "l"(src) : "memory");
}
__device__ __forceinline__ uint32_t s2u(const void* p) {
    uint32_t a;
    asm("{ .reg .u64 t; cvta.to.shared.u64 t, %1; cvt.u32.u64 %0, t; }"
        : "=r"(a) : "l"(p));
    return a;
}
__device__ __forceinline__ uint32_t f2tf32(float x) {
    uint32_t r;
    asm("cvt.rna.tf32.f32 %0, %1;" : "=r"(r) : "f"(x));
    return r;
}
__device__ __forceinline__ void mma_tf32(float* c, const uint32_t* a, const uint32_t* b) {
    asm volatile(
        "mma.sync.aligned.m16n8k8.row.col.f32.tf32.tf32.f32 "
        "{%0,%1,%2,%3}, {%4,%5,%6,%7}, {%8,%9}, {%0,%1,%2,%3};"
        : "+f"(c[0]), "+f"(c[1]), "+f"(c[2]), "+f"(c[3])
        : "r"(a[0]), "r"(a[1]), "r"(a[2]), "r"(a[3]), "r"(b[0]), "r"(b[1]));
}
__device__ __forceinline__ float gelu_exact(float x) {
    return 0.5f * x * (1.0f + erff(x * 0.7071067811865476f));
}

// =========================== tf32 mma.sync GEMM core ==========================
// C[.,N] tile (MI*32 x 128) = act(A @ W + bias) (+res). K staged by 32.
#define A_LD 36
#define B_LD 132
#define B_STAGE_F (32 * B_LD)     // 4224

template <int MI>
__host__ __device__ constexpr int stage_f() { return MI * 32 * A_LD + B_STAGE_F; }
template <int MI>
__host__ __device__ constexpr int gemm_smem() { return 2 * stage_f<MI>() * 4; }

template <int ACT, bool RES, int MI>
__device__ __forceinline__ void gemm_core(
    const float* __restrict__ A, const float* __restrict__ W,
    const float* __restrict__ bias, const float* __restrict__ res,
    float* __restrict__ C, int N, int K, int m0, int n0, float* smem)
{
    const int BMv = MI * 32;
    const int A_STAGE_F = BMv * A_LD;
    const int STAGE_F = A_STAGE_F + B_STAGE_F;

    const int tid  = threadIdx.x;
    const int wid  = tid >> 5;
    const int lane = tid & 31;
    const int g    = lane >> 2;
    const int tig  = lane & 3;
    const int wm   = wid >> 2;       // 0..1
    const int wn   = wid & 3;        // 0..3

    const uint32_t sb = s2u(smem);

    auto load_stage = [&](int s, int b) {
        const uint32_t abase = sb + (uint32_t)(b * STAGE_F) * 4;
        const uint32_t bbase = abase + A_STAGE_F * 4;
        const float* Ag = A + (size_t)m0 * K + s * 32;
        const float* Wg = W + (size_t)(s * 32) * N + n0;
#pragma unroll
        for (int i = 0; i < MI; i++) {           // A: BMv rows x 8 chunks of 16B
            int c = tid + i * 256;
            int row = c >> 3, k4 = c & 7;
            cp16(abase + row * (A_LD * 4) + k4 * 16,
                 Ag + (size_t)row * K + k4 * 4);
        }
#pragma unroll
        for (int i = 0; i < 4; i++) {            // B: 32 k-rows x 32 chunks of 16B
            int c = tid + i * 256;
            int kr = c >> 5, n4 = c & 31;
            cp16(bbase + kr * (B_LD * 4) + n4 * 16,
                 Wg + (size_t)kr * N + n4 * 4);
        }
        asm volatile("cp.async.commit_group;" ::: "memory");
    };

    float acc[MI][4][4];
#pragma unroll
    for (int mi = 0; mi < MI; mi++)
#pragma unroll
        for (int ni = 0; ni < 4; ni++)
#pragma unroll
            for (int t = 0; t < 4; t++) acc[mi][ni][t] = 0.f;

    const int NS = K / 32;
    load_stage(0, 0);

    for (int s = 0; s < NS; s++) {
        const int buf = s & 1;
        if (s + 1 < NS) {
            load_stage(s + 1, buf ^ 1);
            asm volatile("cp.async.wait_group 1;" ::: "memory");
        } else {
            asm volatile("cp.async.wait_group 0;" ::: "memory");
        }
        __syncthreads();

        const float* As = smem + buf * STAGE_F;
        const float* Bs = As + A_STAGE_F;

#pragma unroll
        for (int ks = 0; ks < 4; ks++) {
            uint32_t afr[MI][4];
#pragma unroll
            for (int mi = 0; mi < MI; mi++) {
                const float* p = As + (wm * (MI * 16) + mi * 16 + g) * A_LD + ks * 8 + tig;
                afr[mi][0] = f2tf32(p[0]);
                afr[mi][1] = f2tf32(p[8 * A_LD]);
                afr[mi][2] = f2tf32(p[4]);
                afr[mi][3] = f2tf32(p[8 * A_LD + 4]);
            }
            uint32_t bfr[4][2];
#pragma unroll
            for (int ni = 0; ni < 4; ni++) {
                const float* p = Bs + (ks * 8 + tig) * B_LD + wn * 32 + ni * 8 + g;
                bfr[ni][0] = f2tf32(p[0]);
                bfr[ni][1] = f2tf32(p[4 * B_LD]);
            }
#pragma unroll
            for (int mi = 0; mi < MI; mi++)
#pragma unroll
                for (int ni = 0; ni < 4; ni++)
                    mma_tf32(acc[mi][ni], afr[mi], bfr[ni]);
        }
        __syncthreads();
    }

#pragma unroll
    for (int mi = 0; mi < MI; mi++) {
        const int r0 = m0 + wm * (MI * 16) + mi * 16 + g;
#pragma unroll
        for (int ni = 0; ni < 4; ni++) {
            const int col = n0 + wn * 32 + ni * 8 + tig * 2;
            const float bx = bias[col], by = bias[col + 1];
#pragma unroll
            for (int hh = 0; hh < 2; hh++) {
                const int row = r0 + hh * 8;
                float cx = acc[mi][ni][hh * 2 + 0] + bx;
                float cy = acc[mi][ni][hh * 2 + 1] + by;
                if (ACT == 1) { cx = gelu_exact(cx); cy = gelu_exact(cy); }
                else if (ACT == 2) { cx = fmaxf(cx, 0.f); cy = fmaxf(cy, 0.f); }
                if (RES) {
                    cx += res[(size_t)row * N + col];
                    cy += res[(size_t)row * N + col + 1];
                }
                *(float2*)(C + (size_t)row * N + col) = make_float2(cx, cy);
            }
        }
    }
}

template <int ACT, bool RES, int MI>
__global__ __launch_bounds__(256) void tc_gemm(
    const float* __restrict__ A, const float* __restrict__ W,
    const float* __restrict__ bias, const float* __restrict__ res,
    float* __restrict__ C, int N, int K)
{
    extern __shared__ float smem[];
    gemm_core<ACT, RES, MI>(A, W, bias, res, C, N, K,
                            blockIdx.y * (MI * 32), blockIdx.x * 128, smem);
}

// fused QKV: grid.x = 24 (3 matrices x 8 col-blocks), grid.y = 32
__global__ __launch_bounds__(256) void qkv_gemm(
    const float* __restrict__ A,
    const float* __restrict__ wq, const float* __restrict__ wk, const float* __restrict__ wv,
    const float* __restrict__ bq, const float* __restrict__ bk, const float* __restrict__ bv,
    float* __restrict__ q, float* __restrict__ k, float* __restrict__ v)
{
    extern __shared__ float smem[];
    const int mat = blockIdx.x >> 3;
    const int n0  = (blockIdx.x & 7) * 128;
    const float* W = (mat == 0) ? wq : (mat == 1) ? wk : wv;
    const float* B = (mat == 0) ? bq : (mat == 1) ? bk : bv;
    float* C       = (mat == 0) ? q  : (mat == 1) ? k  : v;
    gemm_core<0, false, 4>(A, W, B, nullptr, C, C_DIM, C_DIM,
                           blockIdx.y * 128, n0, smem);
}

// ---------------- LayerNorm: one block per row, C=1024 ----------------
__global__ __launch_bounds__(256) void ln_kernel(const float* __restrict__ x,
                                                 const float* __restrict__ g,
                                                 const float* __restrict__ b,
                                                 float* __restrict__ out) {
    __shared__ float red[256];
    const int row = blockIdx.x;
    const int tid = threadIdx.x;
    const float* xr = x + (size_t)row * C_DIM;

    float v[4];
    float s = 0.f;
#pragma unroll
    for (int i = 0; i < 4; i++) { v[i] = xr[tid + i * 256]; s += v[i]; }
    red[tid] = s; __syncthreads();
    for (int off = 128; off > 0; off >>= 1) {
        if (tid < off) red[tid] += red[tid + off];
        __syncthreads();
    }
    const float mean = red[0] * (1.0f / 1024.0f);
    __syncthreads();

    float sq = 0.f;
#pragma unroll
    for (int i = 0; i < 4; i++) { float d = v[i] - mean; sq += d * d; }
    red[tid] = sq; __syncthreads();
    for (int off = 128; off > 0; off >>= 1) {
        if (tid < off) red[tid] += red[tid + off];
        __syncthreads();
    }
    const float inv = rsqrtf(red[0] * (1.0f / 1024.0f) + 1e-5f);

    float* orow = out + (size_t)row * C_DIM;
#pragma unroll
    for (int i = 0; i < 4; i++) {
        int col = tid + i * 256;
        orow[col] = (v[i] - mean) * inv * g[col] + b[col];
    }
}

// ------------- SIMT SGEMM (adapter path only) --------------------------------
template <int ACT, bool RES>
__global__ __launch_bounds__(256) void sgemm_kernel(
    const float* __restrict__ A, const float* __restrict__ B,
    const float* __restrict__ bias, const float* __restrict__ res,
    float* __restrict__ C, int M, int N, int K)
{
    __shared__ float As[16][64];
    __shared__ float Bs[16][64];

    const int tid = threadIdx.x;
    const int m0 = blockIdx.y * 64;
    const int n0 = blockIdx.x * 64;

    const int aRow = tid >> 2;
    const int aK   = (tid & 3) * 4;
    const int bRow = tid >> 4;
    const int bC   = (tid & 15) * 4;
    const int rm   = (tid >> 4) * 4;
    const int cn   = (tid & 15) * 4;

    float acc[4][4];
#pragma unroll
    for (int i = 0; i < 4; i++)
#pragma unroll
        for (int j = 0; j < 4; j++) acc[i][j] = 0.f;

    for (int kt = 0; kt < K; kt += 16) {
        const float4 a4 = *(const float4*)(A + (size_t)(m0 + aRow) * K + kt + aK);
        const float4 b4 = *(const float4*)(B + (size_t)(kt + bRow) * N + n0 + bC);
        __syncthreads();
        As[aK + 0][aRow] = a4.x;
        As[aK + 1][aRow] = a4.y;
        As[aK + 2][aRow] = a4.z;
        As[aK + 3][aRow] = a4.w;
        *(float4*)&Bs[bRow][bC] = b4;
        __syncthreads();
#pragma unroll
        for (int kk = 0; kk < 16; kk++) {
            const float4 av = *(const float4*)&As[kk][rm];
            const float4 bv = *(const float4*)&Bs[kk][cn];
            const float a_[4] = {av.x, av.y, av.z, av.w};
            const float b_[4] = {bv.x, bv.y, bv.z, bv.w};
#pragma unroll
            for (int i = 0; i < 4; i++)
#pragma unroll
                for (int j = 0; j < 4; j++) acc[i][j] += a_[i] * b_[j];
        }
    }

#pragma unroll
    for (int i = 0; i < 4; i++) {
        const int row = m0 + rm + i;
        float4 o;
        float cvals[4];
#pragma unroll
        for (int j = 0; j < 4; j++) {
            const int col = n0 + cn + j;
            float c = acc[i][j] + bias[col];
            if (ACT == 1) c = gelu_exact(c);
            else if (ACT == 2) c = fmaxf(c, 0.f);
            if (RES) c += res[(size_t)row * N + col];
            cvals[j] = c;
        }
        o.x = cvals[0]; o.y = cvals[1]; o.z = cvals[2]; o.w = cvals[3];
        *(float4*)(C + (size_t)row * N + n0 + cn) = o;
    }
}

// ================= Flash attention with tf32 mma.sync ========================
// CTA: 128 threads (4 warps). 64-query tile per CTA, warp owns 16 rows.
// smem: Qs[64][68] (pre-scaled), Ks[64][68], Vt[64][68] (transposed), Ps[4][16][68]
#define ATT_LD 68
#define ATT_SMEM (4 * 64 * ATT_LD * 4)   // 69632 B

__global__ __launch_bounds__(128) void attn_mma(const float* __restrict__ q,
                                                const float* __restrict__ k,
                                                const float* __restrict__ v,
                                                float* __restrict__ y) {
    extern __shared__ float sm[];
    float* Qs = sm;                    // [64][68]
    float* Ks = Qs + 64 * ATT_LD;      // [64][68]
    float* Vt = Ks + 64 * ATT_LD;      // [64][68]  Vt[d][j] = V[j][d]
    float* Ps = Vt + 64 * ATT_LD;      // [4][16][68]

    const int bh = blockIdx.x;         // b*16 + h
    const int b = bh >> 4, h = bh & 15;
    const int qb = blockIdx.y;
    const int tid = threadIdx.x;
    const int w = tid >> 5, lane = tid & 31;
    const int g = lane >> 2, tig = lane & 3;

    const float* qp = q + (size_t)b * T_LEN * C_DIM + h * HDIM;
    const float* kp = k + (size_t)b * T_LEN * C_DIM + h * HDIM;
    const float* vp = v + (size_t)b * T_LEN * C_DIM + h * HDIM;

    // Load Q tile, pre-scaled by 1/sqrt(64)
    {
        const int r = tid >> 1, s0 = (tid & 1) * 32;
        const float* src = qp + (size_t)(qb * 64 + r) * C_DIM + s0;
        float* dst = Qs + r * ATT_LD + s0;
#pragma unroll
        for (int i = 0; i < 8; i++) {
            float4 t = *(const float4*)(src + i * 4);
            t.x *= 0.125f; t.y *= 0.125f; t.z *= 0.125f; t.w *= 0.125f;
            *(float4*)(dst + i * 4) = t;
        }
    }

    float of[8][4];
#pragma unroll
    for (int dc = 0; dc < 8; dc++)
#pragma unroll
        for (int t = 0; t < 4; t++) of[dc][t] = 0.f;
    float mi0 = -1e30f, mi1 = -1e30f, li0 = 0.f, li1 = 0.f;

    const int r_glob0 = qb * 64 + w * 16 + g;       // row for e=0,1
    const int r_glob1 = r_glob0 + 8;                // row for e=2,3

    for (int kb = 0; kb <= qb; kb++) {
        __syncthreads();
        // load K and V(T) tiles
        {
            const int r = tid >> 1, s0 = (tid & 1) * 32;
            const float* ks = kp + (size_t)(kb * 64 + r) * C_DIM + s0;
            float* kd = Ks + r * ATT_LD + s0;
#pragma unroll
            for (int i = 0; i < 8; i++)
                *(float4*)(kd + i * 4) = *(const float4*)(ks + i * 4);
            const float* vs = vp + (size_t)(kb * 64 + r) * C_DIM + s0;
#pragma unroll
            for (int i = 0; i < 8; i++) {
                float4 t = *(const float4*)(vs + i * 4);
                const int d = s0 + i * 4;
                Vt[(d + 0) * ATT_LD + r] = t.x;
                Vt[(d + 1) * ATT_LD + r] = t.y;
                Vt[(d + 2) * ATT_LD + r] = t.z;
                Vt[(d + 3) * ATT_LD + r] = t.w;
            }
        }
        __syncthreads();

        // S = Q K^T  (warp rows w*16..w*16+15, cols 64)
        float sf[8][4];
#pragma unroll
        for (int nc = 0; nc < 8; nc++)
#pragma unroll
            for (int t = 0; t < 4; t++) sf[nc][t] = 0.f;
#pragma unroll
        for (int kc = 0; kc < 8; kc++) {
            uint32_t af[4];
            const float* ap = Qs + (w * 16 + g) * ATT_LD + kc * 8 + tig;
            af[0] = f2tf32(ap[0]);
            af[1] = f2tf32(ap[8 * ATT_LD]);
            af[2] = f2tf32(ap[4]);
            af[3] = f2tf32(ap[8 * ATT_LD + 4]);
#pragma unroll
            for (int nc = 0; nc < 8; nc++) {
                uint32_t bf[2];
                const float* bp = Ks + (nc * 8 + g) * ATT_LD + kc * 8 + tig;
                bf[0] = f2tf32(bp[0]);
                bf[1] = f2tf32(bp[4]);
                mma_tf32(sf[nc], af, bf);
            }
        }

        // causal mask (diag block only)
        if (kb == qb) {
#pragma unroll
            for (int nc = 0; nc < 8; nc++) {
                const int j0 = kb * 64 + nc * 8 + 2 * tig;
                if (j0 > r_glob0)     sf[nc][0] = -1e30f;
                if (j0 + 1 > r_glob0) sf[nc][1] = -1e30f;
                if (j0 > r_glob1)     sf[nc][2] = -1e30f;
                if (j0 + 1 > r_glob1) sf[nc][3] = -1e30f;
            }
        }

        // online softmax (rows g, g+8; quad holds full 64-col row)
        float ml0 = -1e30f, ml1 = -1e30f;
#pragma unroll
        for (int nc = 0; nc < 8; nc++) {
            ml0 = fmaxf(ml0, fmaxf(sf[nc][0], sf[nc][1]));
            ml1 = fmaxf(ml1, fmaxf(sf[nc][2], sf[nc][3]));
        }
        ml0 = fmaxf(ml0, __shfl_xor_sync(0xFFFFFFFF, ml0, 1));
        ml0 = fmaxf(ml0, __shfl_xor_sync(0xFFFFFFFF, ml0, 2));
        ml1 = fmaxf(ml1, __shfl_xor_sync(0xFFFFFFFF, ml1, 1));
        ml1 = fmaxf(ml1, __shfl_xor_sync(0xFFFFFFFF, ml1, 2));

        const float mn0 = fmaxf(mi0, ml0), mn1 = fmaxf(mi1, ml1);
        const float al0 = __expf(mi0 - mn0), al1 = __expf(mi1 - mn1);
        li0 *= al0; li1 *= al1;
#pragma unroll
        for (int dc = 0; dc < 8; dc++) {
            of[dc][0] *= al0; of[dc][1] *= al0;
            of[dc][2] *= al1; of[dc][3] *= al1;
        }
#pragma unroll
        for (int nc = 0; nc < 8; nc++) {
            sf[nc][0] = __expf(sf[nc][0] - mn0);
            sf[nc][1] = __expf(sf[nc][1] - mn0);
            sf[nc][2] = __expf(sf[nc][2] - mn1);
            sf[nc][3] = __expf(sf[nc][3] - mn1);
            li0 += sf[nc][0] + sf[nc][1];
            li1 += sf[nc][2] + sf[nc][3];
        }
        mi0 = mn0; mi1 = mn1;

        // write P to per-warp smem, reload as A-frags
        float* pw = Ps + w * 16 * ATT_LD;
#pragma unroll
        for (int nc = 0; nc < 8; nc++) {
            pw[g * ATT_LD + nc * 8 + 2 * tig]           = sf[nc][0];
            pw[g * ATT_LD + nc * 8 + 2 * tig + 1]       = sf[nc][1];
            pw[(g + 8) * ATT_LD + nc * 8 + 2 * tig]     = sf[nc][2];
            pw[(g + 8) * ATT_LD + nc * 8 + 2 * tig + 1] = sf[nc][3];
        }
        __syncwarp();

        // O += P @ V
#pragma unroll
        for (int kc = 0; kc < 8; kc++) {
            uint32_t pf[4];
            const float* pp = pw + g * ATT_LD + kc * 8 + tig;
            pf[0] = f2tf32(pp[0]);
            pf[1] = f2tf32(pp[8 * ATT_LD]);
            pf[2] = f2tf32(pp[4]);
            pf[3] = f2tf32(pp[8 * ATT_LD + 4]);
#pragma unroll
            for (int dc = 0; dc < 8; dc++) {
                uint32_t bf[2];
                const float* vp2 = Vt + (dc * 8 + g) * ATT_LD + kc * 8 + tig;
                bf[0] = f2tf32(vp2[0]);
                bf[1] = f2tf32(vp2[4]);
                mma_tf32(of[dc], pf, bf);
            }
        }
        __syncwarp();
    }

    // finalize: reduce li across quad, normalize, store
    li0 += __shfl_xor_sync(0xFFFFFFFF, li0, 1);
    li0 += __shfl_xor_sync(0xFFFFFFFF, li0, 2);
    li1 += __shfl_xor_sync(0xFFFFFFFF, li1, 1);
    li1 += __shfl_xor_sync(0xFFFFFFFF, li1, 2);
    const float inv0 = 1.f / li0, inv1 = 1.f / li1;

    float* yp = y + ((size_t)b * T_LEN + qb * 64 + w * 16) * C_DIM + h * HDIM;
#pragma unroll
    for (int dc = 0; dc < 8; dc++) {
        const int col = dc * 8 + 2 * tig;
        *(float2*)(yp + (size_t)g * C_DIM + col) =
            make_float2(of[dc][0] * inv0, of[dc][1] * inv0);
        *(float2*)(yp + (size_t)(g + 8) * C_DIM + col) =
            make_float2(of[dc][2] * inv1, of[dc][3] * inv1);
    }
}

// ---------------- final combine: out = 2*hidden + mlp + adapter --------------
__global__ void combine_kernel(const float* __restrict__ hidden,
                               const float* __restrict__ mlp,
                               const float* __restrict__ a,
                               float* __restrict__ out, int n) {
    int i = blockIdx.x * blockDim.x + threadIdx.x;
    if (i < n) out[i] = 2.f * hidden[i] + mlp[i] + a[i];
}

// -----------------------------------------------------------------------------
extern "C" void kernel_launch(void* const* d_in, const int* in_sizes, int n_in,
                              void* d_out, int out_size) {
    const float* x     = (const float*)d_in[0];
    const float* ln1_g = (const float*)d_in[1];
    const float* ln1_b = (const float*)d_in[2];
    const float* ln2_g = (const float*)d_in[3];
    const float* ln2_b = (const float*)d_in[4];
    const float* ln3_g = (const float*)d_in[5];
    const float* ln3_b = (const float*)d_in[6];
    const float* wq = (const float*)d_in[7];   const float* bq = (const float*)d_in[8];
    const float* wk = (const float*)d_in[9];   const float* bk = (const float*)d_in[10];
    const float* wv = (const float*)d_in[11];  const float* bv = (const float*)d_in[12];
    const float* wo = (const float*)d_in[13];  const float* bo = (const float*)d_in[14];
    const float* w1 = (const float*)d_in[15];  const float* b1 = (const float*)d_in[16];
    const float* w2 = (const float*)d_in[17];  const float* b2 = (const float*)d_in[18];
    const float* wd = (const float*)d_in[19];  const float* bd = (const float*)d_in[20];
    const float* wu = (const float*)d_in[21];  const float* bu = (const float*)d_in[22];
    float* out = (float*)d_out;

    float *h, *q, *k, *v, *y, *hidden, *m, *ff, *mlp, *n3, *ad1, *a;
    cudaGetSymbolAddress((void**)&h,      g_h);
    cudaGetSymbolAddress((void**)&q,      g_q);
    cudaGetSymbolAddress((void**)&k,      g_k);
    cudaGetSymbolAddress((void**)&v,      g_v);
    cudaGetSymbolAddress((void**)&y,      g_y);
    cudaGetSymbolAddress((void**)&hidden, g_hidden);
    cudaGetSymbolAddress((void**)&m,      g_m);
    cudaGetSymbolAddress((void**)&ff,     g_ff);
    cudaGetSymbolAddress((void**)&mlp,    g_mlp);
    cudaGetSymbolAddress((void**)&n3,     g_n3);
    cudaGetSymbolAddress((void**)&ad1,    g_ad1);
    cudaGetSymbolAddress((void**)&a,      g_a);

    cudaFuncSetAttribute(qkv_gemm, cudaFuncAttributeMaxDynamicSharedMemorySize, gemm_smem<4>());
    cudaFuncSetAttribute(tc_gemm<1, false, 4>, cudaFuncAttributeMaxDynamicSharedMemorySize, gemm_smem<4>());
    cudaFuncSetAttribute(tc_gemm<0, true, 2>,  cudaFuncAttributeMaxDynamicSharedMemorySize, gemm_smem<2>());
    cudaFuncSetAttribute(tc_gemm<0, false, 2>, cudaFuncAttributeMaxDynamicSharedMemorySize, gemm_smem<2>());
    cudaFuncSetAttribute(attn_mma, cudaFuncAttributeMaxDynamicSharedMemorySize, ATT_SMEM);

    // LN1(x), LN3(x)
    ln_kernel<<<M_ROWS, 256>>>(x, ln1_g, ln1_b, h);
    ln_kernel<<<M_ROWS, 256>>>(x, ln3_g, ln3_b, n3);

    // fused QKV projection (grid 24x32 = 768 CTAs)
    qkv_gemm<<<dim3(24, 32), 256, gemm_smem<4>()>>>(h, wq, wk, wv, bq, bk, bv, q, k, v);

    // Causal attention (tensor cores)
    attn_mma<<<dim3(4 * NHEAD, T_LEN / 64), 128, ATT_SMEM>>>(q, k, v, y);

    // Output projection + residual -> hidden  (BM=64 tiles: grid 8x64 = 512)
    tc_gemm<0, true, 2><<<dim3(8, 64), 256, gemm_smem<2>()>>>(y, wo, bo, x, hidden, C_DIM, C_DIM);

    // MLP on ln2(hidden)
    ln_kernel<<<M_ROWS, 256>>>(hidden, ln2_g, ln2_b, m);
    tc_gemm<1, false, 4><<<dim3(32, 32), 256, gemm_smem<4>()>>>(m, w1, b1, nullptr, ff, FF_DIM, C_DIM);
    tc_gemm<0, false, 2><<<dim3(8, 64), 256, gemm_smem<2>()>>>(ff, w2, b2, nullptr, mlp, C_DIM, FF_DIM);

    // Adapter on ln3(x) (small; SIMT fp32)
    dim3 gCA(A_DIM / 64, M_ROWS / 64);
    sgemm_kernel<2, false><<<gCA, 256>>>(n3, wd, bd, nullptr, ad1, M_ROWS, A_DIM, C_DIM);
    dim3 gAU(C_DIM / 64, M_ROWS / 64);
    sgemm_kernel<0, false><<<gAU, 256>>>(ad1, wu, bu, nullptr, a, M_ROWS, C_DIM, A_DIM);

    // out = 2*hidden + mlp + adapter
    const int n = M_ROWS * C_DIM;
    combine_kernel<<<(n + 255) / 256, 256>>>(hidden, mlp, a, out, n);
}

// round 5
// speedup vs baseline: 3.2664x; 1.0601x over previous
#include <cuda_runtime.h>
#include <math.h>
#include <stdint.h>

// Shapes
#define M_ROWS 4096   // B*T
#define C_DIM  1024
#define FF_DIM 4096
#define A_DIM  64
#define T_LEN  1024
#define NHEAD  16
#define HDIM   64

// ---------------- scratch (device globals; no allocs allowed) ----------------
__device__ float g_h     [M_ROWS * C_DIM];
__device__ float g_q     [M_ROWS * C_DIM];
__device__ float g_k     [M_ROWS * C_DIM];
__device__ float g_v     [M_ROWS * C_DIM];
__device__ float g_y     [M_ROWS * C_DIM];
__device__ float g_hidden[M_ROWS * C_DIM];
__device__ float g_m     [M_ROWS * C_DIM];
__device__ float g_ff    [M_ROWS * FF_DIM];
__device__ float g_mlp   [M_ROWS * C_DIM];
__device__ float g_n3    [M_ROWS * C_DIM];
__device__ float g_ad1   [M_ROWS * A_DIM];
__device__ float g_a     [M_ROWS * C_DIM];

// ======================= helpers ==============================================
__device__ __forceinline__ void cp16(uint32_t dst, const void* src) {
    asm volatile("cp.async.cg.shared.global [%0], [%1], 16;"
                 :: "r"(dst), "l"(src) : "memory");
}
__device__ __forceinline__ uint32_t s2u(const void* p) {
    uint32_t a;
    asm("{ .reg .u64 t; cvta.to.shared.u64 t, %1; cvt.u32.u64 %0, t; }"
        : "=r"(a) : "l"(p));
    return a;
}
// Raw fp32 bits fed to tf32 mma: HW uses top 19 bits (RZ-equivalent).
__device__ __forceinline__ uint32_t f2tf32(float x) { return __float_as_uint(x); }

__device__ __forceinline__ void mma_tf32(float* c, const uint32_t* a, const uint32_t* b) {
    asm volatile(
        "mma.sync.aligned.m16n8k8.row.col.f32.tf32.tf32.f32 "
        "{%0,%1,%2,%3}, {%4,%5,%6,%7}, {%8,%9}, {%0,%1,%2,%3};"
        : "+f"(c[0]), "+f"(c[1]), "+f"(c[2]), "+f"(c[3])
        : "r"(a[0]), "r"(a[1]), "r"(a[2]), "r"(a[3]), "r"(b[0]), "r"(b[1]));
}
__device__ __forceinline__ float gelu_exact(float x) {
    return 0.5f * x * (1.0f + erff(x * 0.7071067811865476f));
}

// =========================== tf32 mma.sync GEMM core ==========================
#define A_LD 36
#define B_LD 132
#define B_STAGE_F (32 * B_LD)     // 4224

template <int MI>
__host__ __device__ constexpr int stage_f() { return MI * 32 * A_LD + B_STAGE_F; }
template <int MI>
__host__ __device__ constexpr int gemm_smem() { return 2 * stage_f<MI>() * 4; }

template <int ACT, bool RES, int MI>
__device__ __forceinline__ void gemm_core(
    const float* __restrict__ A, const float* __restrict__ W,
    const float* __restrict__ bias, const float* __restrict__ res,
    float* __restrict__ C, int N, int K, int m0, int n0, float* smem)
{
    const int BMv = MI * 32;
    const int A_STAGE_F = BMv * A_LD;
    const int STAGE_F = A_STAGE_F + B_STAGE_F;

    const int tid  = threadIdx.x;
    const int wid  = tid >> 5;
    const int lane = tid & 31;
    const int g    = lane >> 2;
    const int tig  = lane & 3;
    const int wm   = wid >> 2;       // 0..1
    const int wn   = wid & 3;        // 0..3

    const uint32_t sb = s2u(smem);

    auto load_stage = [&](int s, int b) {
        const uint32_t abase = sb + (uint32_t)(b * STAGE_F) * 4;
        const uint32_t bbase = abase + A_STAGE_F * 4;
        const float* Ag = A + (size_t)m0 * K + s * 32;
        const float* Wg = W + (size_t)(s * 32) * N + n0;
#pragma unroll
        for (int i = 0; i < MI; i++) {
            int c = tid + i * 256;
            int row = c >> 3, k4 = c & 7;
            cp16(abase + row * (A_LD * 4) + k4 * 16,
                 Ag + (size_t)row * K + k4 * 4);
        }
#pragma unroll
        for (int i = 0; i < 4; i++) {
            int c = tid + i * 256;
            int kr = c >> 5, n4 = c & 31;
            cp16(bbase + kr * (B_LD * 4) + n4 * 16,
                 Wg + (size_t)kr * N + n4 * 4);
        }
        asm volatile("cp.async.commit_group;" ::: "memory");
    };

    float acc[MI][4][4];
#pragma unroll
    for (int mi = 0; mi < MI; mi++)
#pragma unroll
        for (int ni = 0; ni < 4; ni++)
#pragma unroll
            for (int t = 0; t < 4; t++) acc[mi][ni][t] = 0.f;

    const int NS = K / 32;
    load_stage(0, 0);

    for (int s = 0; s < NS; s++) {
        const int buf = s & 1;
        if (s + 1 < NS) {
            load_stage(s + 1, buf ^ 1);
            asm volatile("cp.async.wait_group 1;" ::: "memory");
        } else {
            asm volatile("cp.async.wait_group 0;" ::: "memory");
        }
        __syncthreads();

        const float* As = smem + buf * STAGE_F;
        const float* Bs = As + A_STAGE_F;

#pragma unroll
        for (int ks = 0; ks < 4; ks++) {
            uint32_t afr[MI][4];
#pragma unroll
            for (int mi = 0; mi < MI; mi++) {
                const float* p = As + (wm * (MI * 16) + mi * 16 + g) * A_LD + ks * 8 + tig;
                afr[mi][0] = f2tf32(p[0]);
                afr[mi][1] = f2tf32(p[8 * A_LD]);
                afr[mi][2] = f2tf32(p[4]);
                afr[mi][3] = f2tf32(p[8 * A_LD + 4]);
            }
            uint32_t bfr[4][2];
#pragma unroll
            for (int ni = 0; ni < 4; ni++) {
                const float* p = Bs + (ks * 8 + tig) * B_LD + wn * 32 + ni * 8 + g;
                bfr[ni][0] = f2tf32(p[0]);
                bfr[ni][1] = f2tf32(p[4 * B_LD]);
            }
#pragma unroll
            for (int mi = 0; mi < MI; mi++)
#pragma unroll
                for (int ni = 0; ni < 4; ni++)
                    mma_tf32(acc[mi][ni], afr[mi], bfr[ni]);
        }
        __syncthreads();
    }

#pragma unroll
    for (int mi = 0; mi < MI; mi++) {
        const int r0 = m0 + wm * (MI * 16) + mi * 16 + g;
#pragma unroll
        for (int ni = 0; ni < 4; ni++) {
            const int col = n0 + wn * 32 + ni * 8 + tig * 2;
            const float bx = bias[col], by = bias[col + 1];
#pragma unroll
            for (int hh = 0; hh < 2; hh++) {
                const int row = r0 + hh * 8;
                float cx = acc[mi][ni][hh * 2 + 0] + bx;
                float cy = acc[mi][ni][hh * 2 + 1] + by;
                if (ACT == 1) { cx = gelu_exact(cx); cy = gelu_exact(cy); }
                else if (ACT == 2) { cx = fmaxf(cx, 0.f); cy = fmaxf(cy, 0.f); }
                if (RES) {
                    cx += res[(size_t)row * N + col];
                    cy += res[(size_t)row * N + col + 1];
                }
                *(float2*)(C + (size_t)row * N + col) = make_float2(cx, cy);
            }
        }
    }
}

template <int ACT, bool RES, int MI>
__global__ __launch_bounds__(256) void tc_gemm(
    const float* __restrict__ A, const float* __restrict__ W,
    const float* __restrict__ bias, const float* __restrict__ res,
    float* __restrict__ C, int N, int K)
{
    extern __shared__ float smem[];
    gemm_core<ACT, RES, MI>(A, W, bias, res, C, N, K,
                            blockIdx.y * (MI * 32), blockIdx.x * 128, smem);
}

// fused QKV: grid.x = 24 (3 matrices x 8 col-blocks), grid.y = 32
__global__ __launch_bounds__(256) void qkv_gemm(
    const float* __restrict__ A,
    const float* __restrict__ wq, const float* __restrict__ wk, const float* __restrict__ wv,
    const float* __restrict__ bq, const float* __restrict__ bk, const float* __restrict__ bv,
    float* __restrict__ q, float* __restrict__ k, float* __restrict__ v)
{
    extern __shared__ float smem[];
    const int mat = blockIdx.x >> 3;
    const int n0  = (blockIdx.x & 7) * 128;
    const float* W = (mat == 0) ? wq : (mat == 1) ? wk : wv;
    const float* B = (mat == 0) ? bq : (mat == 1) ? bk : bv;
    float* C       = (mat == 0) ? q  : (mat == 1) ? k  : v;
    gemm_core<0, false, 4>(A, W, B, nullptr, C, C_DIM, C_DIM,
                           blockIdx.y * 128, n0, smem);
}

// ---------------- LayerNorm: one block per row, C=1024 ----------------
__global__ __launch_bounds__(256) void ln_kernel(const float* __restrict__ x,
                                                 const float* __restrict__ g,
                                                 const float* __restrict__ b,
                                                 float* __restrict__ out) {
    __shared__ float red[256];
    const int row = blockIdx.x;
    const int tid = threadIdx.x;
    const float* xr = x + (size_t)row * C_DIM;

    float v[4];
    float s = 0.f;
#pragma unroll
    for (int i = 0; i < 4; i++) { v[i] = xr[tid + i * 256]; s += v[i]; }
    red[tid] = s; __syncthreads();
    for (int off = 128; off > 0; off >>= 1) {
        if (tid < off) red[tid] += red[tid + off];
        __syncthreads();
    }
    const float mean = red[0] * (1.0f / 1024.0f);
    __syncthreads();

    float sq = 0.f;
#pragma unroll
    for (int i = 0; i < 4; i++) { float d = v[i] - mean; sq += d * d; }
    red[tid] = sq; __syncthreads();
    for (int off = 128; off > 0; off >>= 1) {
        if (tid < off) red[tid] += red[tid + off];
        __syncthreads();
    }
    const float inv = rsqrtf(red[0] * (1.0f / 1024.0f) + 1e-5f);

    float* orow = out + (size_t)row * C_DIM;
#pragma unroll
    for (int i = 0; i < 4; i++) {
        int col = tid + i * 256;
        orow[col] = (v[i] - mean) * inv * g[col] + b[col];
    }
}

// ------------- SIMT SGEMM (adapter path only) --------------------------------
template <int ACT, bool RES>
__global__ __launch_bounds__(256) void sgemm_kernel(
    const float* __restrict__ A, const float* __restrict__ B,
    const float* __restrict__ bias, const float* __restrict__ res,
    float* __restrict__ C, int M, int N, int K)
{
    __shared__ float As[16][64];
    __shared__ float Bs[16][64];

    const int tid = threadIdx.x;
    const int m0 = blockIdx.y * 64;
    const int n0 = blockIdx.x * 64;

    const int aRow = tid >> 2;
    const int aK   = (tid & 3) * 4;
    const int bRow = tid >> 4;
    const int bC   = (tid & 15) * 4;
    const int rm   = (tid >> 4) * 4;
    const int cn   = (tid & 15) * 4;

    float acc[4][4];
#pragma unroll
    for (int i = 0; i < 4; i++)
#pragma unroll
        for (int j = 0; j < 4; j++) acc[i][j] = 0.f;

    for (int kt = 0; kt < K; kt += 16) {
        const float4 a4 = *(const float4*)(A + (size_t)(m0 + aRow) * K + kt + aK);
        const float4 b4 = *(const float4*)(B + (size_t)(kt + bRow) * N + n0 + bC);
        __syncthreads();
        As[aK + 0][aRow] = a4.x;
        As[aK + 1][aRow] = a4.y;
        As[aK + 2][aRow] = a4.z;
        As[aK + 3][aRow] = a4.w;
        *(float4*)&Bs[bRow][bC] = b4;
        __syncthreads();
#pragma unroll
        for (int kk = 0; kk < 16; kk++) {
            const float4 av = *(const float4*)&As[kk][rm];
            const float4 bv = *(const float4*)&Bs[kk][cn];
            const float a_[4] = {av.x, av.y, av.z, av.w};
            const float b_[4] = {bv.x, bv.y, bv.z, bv.w};
#pragma unroll
            for (int i = 0; i < 4; i++)
#pragma unroll
                for (int j = 0; j < 4; j++) acc[i][j] += a_[i] * b_[j];
        }
    }

#pragma unroll
    for (int i = 0; i < 4; i++) {
        const int row = m0 + rm + i;
        float4 o;
        float cvals[4];
#pragma unroll
        for (int j = 0; j < 4; j++) {
            const int col = n0 + cn + j;
            float c = acc[i][j] + bias[col];
            if (ACT == 1) c = gelu_exact(c);
            else if (ACT == 2) c = fmaxf(c, 0.f);
            if (RES) c += res[(size_t)row * N + col];
            cvals[j] = c;
        }
        o.x = cvals[0]; o.y = cvals[1]; o.z = cvals[2]; o.w = cvals[3];
        *(float4*)(C + (size_t)row * N + n0 + cn) = o;
    }
}

// ================= Flash attention with tf32 mma.sync ========================
// CTA: 128 threads (4 warps). 64-query tile per CTA, warp owns 16 rows.
// smem: Qs[64][68] (pre-scaled), Ks[64][68] (aliased by P after S-phase), Vt[64][68]
#define ATT_LD 68
#define ATT_SMEM (3 * 64 * ATT_LD * 4)   // 52224 B

__global__ __launch_bounds__(128) void attn_mma(const float* __restrict__ q,
                                                const float* __restrict__ k,
                                                const float* __restrict__ v,
                                                float* __restrict__ y) {
    extern __shared__ float sm[];
    float* Qs = sm;                    // [64][68]
    float* Ks = Qs + 64 * ATT_LD;      // [64][68]; P aliases this after S phase
    float* Vt = Ks + 64 * ATT_LD;      // [64][68]  Vt[d][j] = V[j][d]

    const int bh = blockIdx.x;
    const int b = bh >> 4, h = bh & 15;
    const int qb = blockIdx.y;
    const int tid = threadIdx.x;
    const int w = tid >> 5, lane = tid & 31;
    const int g = lane >> 2, tig = lane & 3;

    const float* qp = q + (size_t)b * T_LEN * C_DIM + h * HDIM;
    const float* kp = k + (size_t)b * T_LEN * C_DIM + h * HDIM;
    const float* vp = v + (size_t)b * T_LEN * C_DIM + h * HDIM;

    // Load Q tile, pre-scaled by 1/sqrt(64)
    {
        const int r = tid >> 1, s0 = (tid & 1) * 32;
        const float* src = qp + (size_t)(qb * 64 + r) * C_DIM + s0;
        float* dst = Qs + r * ATT_LD + s0;
#pragma unroll
        for (int i = 0; i < 8; i++) {
            float4 t = *(const float4*)(src + i * 4);
            t.x *= 0.125f; t.y *= 0.125f; t.z *= 0.125f; t.w *= 0.125f;
            *(float4*)(dst + i * 4) = t;
        }
    }

    float of[8][4];
#pragma unroll
    for (int dc = 0; dc < 8; dc++)
#pragma unroll
        for (int t = 0; t < 4; t++) of[dc][t] = 0.f;
    float mi0 = -1e30f, mi1 = -1e30f, li0 = 0.f, li1 = 0.f;

    const int r_glob0 = qb * 64 + w * 16 + g;
    const int r_glob1 = r_glob0 + 8;

    for (int kb = 0; kb <= qb; kb++) {
        __syncthreads();
        // load K and V(T) tiles
        {
            const int r = tid >> 1, s0 = (tid & 1) * 32;
            const float* ks = kp + (size_t)(kb * 64 + r) * C_DIM + s0;
            float* kd = Ks + r * ATT_LD + s0;
#pragma unroll
            for (int i = 0; i < 8; i++)
                *(float4*)(kd + i * 4) = *(const float4*)(ks + i * 4);
            const float* vs = vp + (size_t)(kb * 64 + r) * C_DIM + s0;
#pragma unroll
            for (int i = 0; i < 8; i++) {
                float4 t = *(const float4*)(vs + i * 4);
                const int d = s0 + i * 4;
                Vt[(d + 0) * ATT_LD + r] = t.x;
                Vt[(d + 1) * ATT_LD + r] = t.y;
                Vt[(d + 2) * ATT_LD + r] = t.z;
                Vt[(d + 3) * ATT_LD + r] = t.w;
            }
        }
        __syncthreads();

        // S = Q K^T
        float sf[8][4];
#pragma unroll
        for (int nc = 0; nc < 8; nc++)
#pragma unroll
            for (int t = 0; t < 4; t++) sf[nc][t] = 0.f;
#pragma unroll
        for (int kc = 0; kc < 8; kc++) {
            uint32_t af[4];
            const float* ap = Qs + (w * 16 + g) * ATT_LD + kc * 8 + tig;
            af[0] = f2tf32(ap[0]);
            af[1] = f2tf32(ap[8 * ATT_LD]);
            af[2] = f2tf32(ap[4]);
            af[3] = f2tf32(ap[8 * ATT_LD + 4]);
#pragma unroll
            for (int nc = 0; nc < 8; nc++) {
                uint32_t bf[2];
                const float* bp = Ks + (nc * 8 + g) * ATT_LD + kc * 8 + tig;
                bf[0] = f2tf32(bp[0]);
                bf[1] = f2tf32(bp[4]);
                mma_tf32(sf[nc], af, bf);
            }
        }

        if (kb == qb) {
#pragma unroll
            for (int nc = 0; nc < 8; nc++) {
                const int j0 = kb * 64 + nc * 8 + 2 * tig;
                if (j0 > r_glob0)     sf[nc][0] = -1e30f;
                if (j0 + 1 > r_glob0) sf[nc][1] = -1e30f;
                if (j0 > r_glob1)     sf[nc][2] = -1e30f;
                if (j0 + 1 > r_glob1) sf[nc][3] = -1e30f;
            }
        }

        // online softmax
        float ml0 = -1e30f, ml1 = -1e30f;
#pragma unroll
        for (int nc = 0; nc < 8; nc++) {
            ml0 = fmaxf(ml0, fmaxf(sf[nc][0], sf[nc][1]));
            ml1 = fmaxf(ml1, fmaxf(sf[nc][2], sf[nc][3]));
        }
        ml0 = fmaxf(ml0, __shfl_xor_sync(0xFFFFFFFF, ml0, 1));
        ml0 = fmaxf(ml0, __shfl_xor_sync(0xFFFFFFFF, ml0, 2));
        ml1 = fmaxf(ml1, __shfl_xor_sync(0xFFFFFFFF, ml1, 1));
        ml1 = fmaxf(ml1, __shfl_xor_sync(0xFFFFFFFF, ml1, 2));

        const float mn0 = fmaxf(mi0, ml0), mn1 = fmaxf(mi1, ml1);
        const float al0 = __expf(mi0 - mn0), al1 = __expf(mi1 - mn1);
        li0 *= al0; li1 *= al1;
#pragma unroll
        for (int dc = 0; dc < 8; dc++) {
            of[dc][0] *= al0; of[dc][1] *= al0;
            of[dc][2] *= al1; of[dc][3] *= al1;
        }
#pragma unroll
        for (int nc = 0; nc < 8; nc++) {
            sf[nc][0] = __expf(sf[nc][0] - mn0);
            sf[nc][1] = __expf(sf[nc][1] - mn0);
            sf[nc][2] = __expf(sf[nc][2] - mn1);
            sf[nc][3] = __expf(sf[nc][3] - mn1);
            li0 += sf[nc][0] + sf[nc][1];
            li1 += sf[nc][2] + sf[nc][3];
        }
        mi0 = mn0; mi1 = mn1;

        // all warps done reading Ks (S phase) before P overwrites it
        __syncthreads();

        // write P into warp's own 16-row slice of Ks, reload as A-frags
        float* pw = Ks + w * 16 * ATT_LD;
#pragma unroll
        for (int nc = 0; nc < 8; nc++) {
            pw[g * ATT_LD + nc * 8 + 2 * tig]           = sf[nc][0];
            pw[g * ATT_LD + nc * 8 + 2 * tig + 1]       = sf[nc][1];
            pw[(g + 8) * ATT_LD + nc * 8 + 2 * tig]     = sf[nc][2];
            pw[(g + 8) * ATT_LD + nc * 8 + 2 * tig + 1] = sf[nc][3];
        }
        __syncwarp();

        // O += P @ V
#pragma unroll
        for (int kc = 0; kc < 8; kc++) {
            uint32_t pf[4];
            const float* pp = pw + g * ATT_LD + kc * 8 + tig;
            pf[0] = f2tf32(pp[0]);
            pf[1] = f2tf32(pp[8 * ATT_LD]);
            pf[2] = f2tf32(pp[4]);
            pf[3] = f2tf32(pp[8 * ATT_LD + 4]);
#pragma unroll
            for (int dc = 0; dc < 8; dc++) {
                uint32_t bf[2];
                const float* vp2 = Vt + (dc * 8 + g) * ATT_LD + kc * 8 + tig;
                bf[0] = f2tf32(vp2[0]);
                bf[1] = f2tf32(vp2[4]);
                mma_tf32(of[dc], pf, bf);
            }
        }
        __syncwarp();
    }

    li0 += __shfl_xor_sync(0xFFFFFFFF, li0, 1);
    li0 += __shfl_xor_sync(0xFFFFFFFF, li0, 2);
    li1 += __shfl_xor_sync(0xFFFFFFFF, li1, 1);
    li1 += __shfl_xor_sync(0xFFFFFFFF, li1, 2);
    const float inv0 = 1.f / li0, inv1 = 1.f / li1;

    float* yp = y + ((size_t)b * T_LEN + qb * 64 + w * 16) * C_DIM + h * HDIM;
#pragma unroll
    for (int dc = 0; dc < 8; dc++) {
        const int col = dc * 8 + 2 * tig;
        *(float2*)(yp + (size_t)g * C_DIM + col) =
            make_float2(of[dc][0] * inv0, of[dc][1] * inv0);
        *(float2*)(yp + (size_t)(g + 8) * C_DIM + col) =
            make_float2(of[dc][2] * inv1, of[dc][3] * inv1);
    }
}

// ---------------- final combine: out = 2*hidden + mlp + adapter --------------
__global__ void combine_kernel(const float* __restrict__ hidden,
                               const float* __restrict__ mlp,
                               const float* __restrict__ a,
                               float* __restrict__ out, int n) {
    int i = blockIdx.x * blockDim.x + threadIdx.x;
    if (i < n) out[i] = 2.f * hidden[i] + mlp[i] + a[i];
}

// -----------------------------------------------------------------------------
extern "C" void kernel_launch(void* const* d_in, const int* in_sizes, int n_in,
                              void* d_out, int out_size) {
    const float* x     = (const float*)d_in[0];
    const float* ln1_g = (const float*)d_in[1];
    const float* ln1_b = (const float*)d_in[2];
    const float* ln2_g = (const float*)d_in[3];
    const float* ln2_b = (const float*)d_in[4];
    const float* ln3_g = (const float*)d_in[5];
    const float* ln3_b = (const float*)d_in[6];
    const float* wq = (const float*)d_in[7];   const float* bq = (const float*)d_in[8];
    const float* wk = (const float*)d_in[9];   const float* bk = (const float*)d_in[10];
    const float* wv = (const float*)d_in[11];  const float* bv = (const float*)d_in[12];
    const float* wo = (const float*)d_in[13];  const float* bo = (const float*)d_in[14];
    const float* w1 = (const float*)d_in[15];  const float* b1 = (const float*)d_in[16];
    const float* w2 = (const float*)d_in[17];  const float* b2 = (const float*)d_in[18];
    const float* wd = (const float*)d_in[19];  const float* bd = (const float*)d_in[20];
    const float* wu = (const float*)d_in[21];  const float* bu = (const float*)d_in[22];
    float* out = (float*)d_out;

    float *h, *q, *k, *v, *y, *hidden, *m, *ff, *mlp, *n3, *ad1, *a;
    cudaGetSymbolAddress((void**)&h,      g_h);
    cudaGetSymbolAddress((void**)&q,      g_q);
    cudaGetSymbolAddress((void**)&k,      g_k);
    cudaGetSymbolAddress((void**)&v,      g_v);
    cudaGetSymbolAddress((void**)&y,      g_y);
    cudaGetSymbolAddress((void**)&hidden, g_hidden);
    cudaGetSymbolAddress((void**)&m,      g_m);
    cudaGetSymbolAddress((void**)&ff,     g_ff);
    cudaGetSymbolAddress((void**)&mlp,    g_mlp);
    cudaGetSymbolAddress((void**)&n3,     g_n3);
    cudaGetSymbolAddress((void**)&ad1,    g_ad1);
    cudaGetSymbolAddress((void**)&a,      g_a);

    cudaFuncSetAttribute(qkv_gemm, cudaFuncAttributeMaxDynamicSharedMemorySize, gemm_smem<4>());
    cudaFuncSetAttribute(tc_gemm<1, false, 4>, cudaFuncAttributeMaxDynamicSharedMemorySize, gemm_smem<4>());
    cudaFuncSetAttribute(tc_gemm<0, true, 2>,  cudaFuncAttributeMaxDynamicSharedMemorySize, gemm_smem<2>());
    cudaFuncSetAttribute(tc_gemm<0, false, 2>, cudaFuncAttributeMaxDynamicSharedMemorySize, gemm_smem<2>());
    cudaFuncSetAttribute(attn_mma, cudaFuncAttributeMaxDynamicSharedMemorySize, ATT_SMEM);

    // LN1(x), LN3(x)
    ln_kernel<<<M_ROWS, 256>>>(x, ln1_g, ln1_b, h);
    ln_kernel<<<M_ROWS, 256>>>(x, ln3_g, ln3_b, n3);

    // fused QKV projection
    qkv_gemm<<<dim3(24, 32), 256, gemm_smem<4>()>>>(h, wq, wk, wv, bq, bk, bv, q, k, v);

    // Causal attention (tensor cores)
    attn_mma<<<dim3(4 * NHEAD, T_LEN / 64), 128, ATT_SMEM>>>(q, k, v, y);

    // Output projection + residual -> hidden
    tc_gemm<0, true, 2><<<dim3(8, 64), 256, gemm_smem<2>()>>>(y, wo, bo, x, hidden, C_DIM, C_DIM);

    // MLP on ln2(hidden)
    ln_kernel<<<M_ROWS, 256>>>(hidden, ln2_g, ln2_b, m);
    tc_gemm<1, false, 4><<<dim3(32, 32), 256, gemm_smem<4>()>>>(m, w1, b1, nullptr, ff, FF_DIM, C_DIM);
    tc_gemm<0, false, 2><<<dim3(8, 64), 256, gemm_smem<2>()>>>(ff, w2, b2, nullptr, mlp, C_DIM, FF_DIM);

    // Adapter on ln3(x) (small; SIMT fp32)
    dim3 gCA(A_DIM / 64, M_ROWS / 64);
    sgemm_kernel<2, false><<<gCA, 256>>>(n3, wd, bd, nullptr, ad1, M_ROWS, A_DIM, C_DIM);
    dim3 gAU(C_DIM / 64, M_ROWS / 64);
    sgemm_kernel<0, false><<<gAU, 256>>>(ad1, wu, bu, nullptr, a, M_ROWS, C_DIM, A_DIM);

    // out = 2*hidden + mlp + adapter
    const int n = M_ROWS * C_DIM;
    combine_kernel<<<(n + 255) / 256, 256>>>(hidden, mlp, a, out, n);
}

// round 6
// speedup vs baseline: 3.3282x; 1.0189x over previous
#include <cuda_runtime.h>
#include <math.h>
#include <stdint.h>

// Shapes
#define M_ROWS 4096   // B*T
#define C_DIM  1024
#define FF_DIM 4096
#define A_DIM  64
#define T_LEN  1024
#define NHEAD  16
#define HDIM   64

// ---------------- scratch (device globals; no allocs allowed) ----------------
__device__ float g_h     [M_ROWS * C_DIM];
__device__ float g_q     [M_ROWS * C_DIM];
__device__ float g_k     [M_ROWS * C_DIM];
__device__ float g_v     [M_ROWS * C_DIM];
__device__ float g_y     [M_ROWS * C_DIM];
__device__ float g_hidden[M_ROWS * C_DIM];
__device__ float g_m     [M_ROWS * C_DIM];
__device__ float g_ff    [M_ROWS * FF_DIM];
__device__ float g_mlp   [M_ROWS * C_DIM];
__device__ float g_n3    [M_ROWS * C_DIM];
__device__ float g_ad1   [M_ROWS * A_DIM];
__device__ float g_a     [M_ROWS * C_DIM];

// ======================= helpers ==============================================
__device__ __forceinline__ void cp16(uint32_t dst, const void* src) {
    asm volatile("cp.async.cg.shared.global [%0], [%1], 16;"
                 :: "r"(dst), "l"(src) : "memory");
}
__device__ __forceinline__ uint32_t s2u(const void* p) {
    uint32_t a;
    asm("{ .reg .u64 t; cvta.to.shared.u64 t, %1; cvt.u32.u64 %0, t; }"
        : "=r"(a) : "l"(p));
    return a;
}
// Raw fp32 bits fed to tf32 mma: HW uses top 19 bits (RZ-equivalent).
__device__ __forceinline__ uint32_t f2tf32(float x) { return __float_as_uint(x); }

// ldmatrix on fp32 data: each 32-bit reg = one float.
// x4: full tf32 A-fragment for a 16x8 tile (rows via lanes 0-15, +4-col via lanes 16-31).
__device__ __forceinline__ void ldsm_x4(uint32_t* r, uint32_t addr) {
    asm volatile("ldmatrix.sync.aligned.m8n8.x4.shared.b16 {%0,%1,%2,%3}, [%4];"
                 : "=r"(r[0]), "=r"(r[1]), "=r"(r[2]), "=r"(r[3]) : "r"(addr));
}
// x2: tf32 B-fragment for an 8(n)x8(k) tile stored (n,k)-row-major.
__device__ __forceinline__ void ldsm_x2(uint32_t* r, uint32_t addr) {
    asm volatile("ldmatrix.sync.aligned.m8n8.x2.shared.b16 {%0,%1}, [%2];"
                 : "=r"(r[0]), "=r"(r[1]) : "r"(addr));
}

__device__ __forceinline__ void mma_tf32(float* c, const uint32_t* a, const uint32_t* b) {
    asm volatile(
        "mma.sync.aligned.m16n8k8.row.col.f32.tf32.tf32.f32 "
        "{%0,%1,%2,%3}, {%4,%5,%6,%7}, {%8,%9}, {%0,%1,%2,%3};"
        : "+f"(c[0]), "+f"(c[1]), "+f"(c[2]), "+f"(c[3])
        : "r"(a[0]), "r"(a[1]), "r"(a[2]), "r"(a[3]), "r"(b[0]), "r"(b[1]));
}
__device__ __forceinline__ float gelu_exact(float x) {
    return 0.5f * x * (1.0f + erff(x * 0.7071067811865476f));
}

// =========================== tf32 mma.sync GEMM core ==========================
#define A_LD 36
#define B_LD 132
#define B_STAGE_F (32 * B_LD)     // 4224

template <int MI>
__host__ __device__ constexpr int stage_f() { return MI * 32 * A_LD + B_STAGE_F; }
template <int MI>
__host__ __device__ constexpr int gemm_smem() { return 2 * stage_f<MI>() * 4; }

template <int ACT, bool RES, int MI>
__device__ __forceinline__ void gemm_core(
    const float* __restrict__ A, const float* __restrict__ W,
    const float* __restrict__ bias, const float* __restrict__ res,
    float* __restrict__ C, int N, int K, int m0, int n0, float* smem)
{
    const int BMv = MI * 32;
    const int A_STAGE_F = BMv * A_LD;
    const int STAGE_F = A_STAGE_F + B_STAGE_F;

    const int tid  = threadIdx.x;
    const int wid  = tid >> 5;
    const int lane = tid & 31;
    const int g    = lane >> 2;
    const int tig  = lane & 3;
    const int wm   = wid >> 2;       // 0..1
    const int wn   = wid & 3;        // 0..3

    // ldmatrix lane addressing for A-fragments
    const int a_lrow = lane & 15;            // row within 16-row tile
    const int a_koff = (lane >> 4) * 4;      // 0 or 4 (k half)

    const uint32_t sb = s2u(smem);

    auto load_stage = [&](int s, int b) {
        const uint32_t abase = sb + (uint32_t)(b * STAGE_F) * 4;
        const uint32_t bbase = abase + A_STAGE_F * 4;
        const float* Ag = A + (size_t)m0 * K + s * 32;
        const float* Wg = W + (size_t)(s * 32) * N + n0;
#pragma unroll
        for (int i = 0; i < MI; i++) {
            int c = tid + i * 256;
            int row = c >> 3, k4 = c & 7;
            cp16(abase + row * (A_LD * 4) + k4 * 16,
                 Ag + (size_t)row * K + k4 * 4);
        }
#pragma unroll
        for (int i = 0; i < 4; i++) {
            int c = tid + i * 256;
            int kr = c >> 5, n4 = c & 31;
            cp16(bbase + kr * (B_LD * 4) + n4 * 16,
                 Wg + (size_t)kr * N + n4 * 4);
        }
        asm volatile("cp.async.commit_group;" ::: "memory");
    };

    float acc[MI][4][4];
#pragma unroll
    for (int mi = 0; mi < MI; mi++)
#pragma unroll
        for (int ni = 0; ni < 4; ni++)
#pragma unroll
            for (int t = 0; t < 4; t++) acc[mi][ni][t] = 0.f;

    const int NS = K / 32;
    load_stage(0, 0);

    for (int s = 0; s < NS; s++) {
        const int buf = s & 1;
        if (s + 1 < NS) {
            load_stage(s + 1, buf ^ 1);
            asm volatile("cp.async.wait_group 1;" ::: "memory");
        } else {
            asm volatile("cp.async.wait_group 0;" ::: "memory");
        }
        __syncthreads();

        const uint32_t As_u = sb + (uint32_t)(buf * STAGE_F) * 4;
        const float* Bs = smem + buf * STAGE_F + A_STAGE_F;

#pragma unroll
        for (int ks = 0; ks < 4; ks++) {
            uint32_t afr[MI][4];
#pragma unroll
            for (int mi = 0; mi < MI; mi++) {
                const uint32_t ad = As_u +
                    (uint32_t)((wm * (MI * 16) + mi * 16 + a_lrow) * A_LD + ks * 8 + a_koff) * 4;
                ldsm_x4(afr[mi], ad);
            }
            uint32_t bfr[4][2];
#pragma unroll
            for (int ni = 0; ni < 4; ni++) {
                const float* p = Bs + (ks * 8 + tig) * B_LD + wn * 32 + ni * 8 + g;
                bfr[ni][0] = f2tf32(p[0]);
                bfr[ni][1] = f2tf32(p[4 * B_LD]);
            }
#pragma unroll
            for (int mi = 0; mi < MI; mi++)
#pragma unroll
                for (int ni = 0; ni < 4; ni++)
                    mma_tf32(acc[mi][ni], afr[mi], bfr[ni]);
        }
        __syncthreads();
    }

#pragma unroll
    for (int mi = 0; mi < MI; mi++) {
        const int r0 = m0 + wm * (MI * 16) + mi * 16 + g;
#pragma unroll
        for (int ni = 0; ni < 4; ni++) {
            const int col = n0 + wn * 32 + ni * 8 + tig * 2;
            const float bx = bias[col], by = bias[col + 1];
#pragma unroll
            for (int hh = 0; hh < 2; hh++) {
                const int row = r0 + hh * 8;
                float cx = acc[mi][ni][hh * 2 + 0] + bx;
                float cy = acc[mi][ni][hh * 2 + 1] + by;
                if (ACT == 1) { cx = gelu_exact(cx); cy = gelu_exact(cy); }
                else if (ACT == 2) { cx = fmaxf(cx, 0.f); cy = fmaxf(cy, 0.f); }
                if (RES) {
                    cx += res[(size_t)row * N + col];
                    cy += res[(size_t)row * N + col + 1];
                }
                *(float2*)(C + (size_t)row * N + col) = make_float2(cx, cy);
            }
        }
    }
}

template <int ACT, bool RES, int MI>
__global__ __launch_bounds__(256) void tc_gemm(
    const float* __restrict__ A, const float* __restrict__ W,
    const float* __restrict__ bias, const float* __restrict__ res,
    float* __restrict__ C, int N, int K)
{
    extern __shared__ float smem[];
    gemm_core<ACT, RES, MI>(A, W, bias, res, C, N, K,
                            blockIdx.y * (MI * 32), blockIdx.x * 128, smem);
}

// fused QKV: grid.x = 24 (3 matrices x 8 col-blocks), grid.y = 32
__global__ __launch_bounds__(256) void qkv_gemm(
    const float* __restrict__ A,
    const float* __restrict__ wq, const float* __restrict__ wk, const float* __restrict__ wv,
    const float* __restrict__ bq, const float* __restrict__ bk, const float* __restrict__ bv,
    float* __restrict__ q, float* __restrict__ k, float* __restrict__ v)
{
    extern __shared__ float smem[];
    const int mat = blockIdx.x >> 3;
    const int n0  = (blockIdx.x & 7) * 128;
    const float* W = (mat == 0) ? wq : (mat == 1) ? wk : wv;
    const float* B = (mat == 0) ? bq : (mat == 1) ? bk : bv;
    float* C       = (mat == 0) ? q  : (mat == 1) ? k  : v;
    gemm_core<0, false, 4>(A, W, B, nullptr, C, C_DIM, C_DIM,
                           blockIdx.y * 128, n0, smem);
}

// ---------------- LayerNorm: one block per row, C=1024 ----------------
__global__ __launch_bounds__(256) void ln_kernel(const float* __restrict__ x,
                                                 const float* __restrict__ g,
                                                 const float* __restrict__ b,
                                                 float* __restrict__ out) {
    __shared__ float red[256];
    const int row = blockIdx.x;
    const int tid = threadIdx.x;
    const float* xr = x + (size_t)row * C_DIM;

    float v[4];
    float s = 0.f;
#pragma unroll
    for (int i = 0; i < 4; i++) { v[i] = xr[tid + i * 256]; s += v[i]; }
    red[tid] = s; __syncthreads();
    for (int off = 128; off > 0; off >>= 1) {
        if (tid < off) red[tid] += red[tid + off];
        __syncthreads();
    }
    const float mean = red[0] * (1.0f / 1024.0f);
    __syncthreads();

    float sq = 0.f;
#pragma unroll
    for (int i = 0; i < 4; i++) { float d = v[i] - mean; sq += d * d; }
    red[tid] = sq; __syncthreads();
    for (int off = 128; off > 0; off >>= 1) {
        if (tid < off) red[tid] += red[tid + off];
        __syncthreads();
    }
    const float inv = rsqrtf(red[0] * (1.0f / 1024.0f) + 1e-5f);

    float* orow = out + (size_t)row * C_DIM;
#pragma unroll
    for (int i = 0; i < 4; i++) {
        int col = tid + i * 256;
        orow[col] = (v[i] - mean) * inv * g[col] + b[col];
    }
}

// ------------- SIMT SGEMM (adapter path only) --------------------------------
template <int ACT, bool RES>
__global__ __launch_bounds__(256) void sgemm_kernel(
    const float* __restrict__ A, const float* __restrict__ B,
    const float* __restrict__ bias, const float* __restrict__ res,
    float* __restrict__ C, int M, int N, int K)
{
    __shared__ float As[16][64];
    __shared__ float Bs[16][64];

    const int tid = threadIdx.x;
    const int m0 = blockIdx.y * 64;
    const int n0 = blockIdx.x * 64;

    const int aRow = tid >> 2;
    const int aK   = (tid & 3) * 4;
    const int bRow = tid >> 4;
    const int bC   = (tid & 15) * 4;
    const int rm   = (tid >> 4) * 4;
    const int cn   = (tid & 15) * 4;

    float acc[4][4];
#pragma unroll
    for (int i = 0; i < 4; i++)
#pragma unroll
        for (int j = 0; j < 4; j++) acc[i][j] = 0.f;

    for (int kt = 0; kt < K; kt += 16) {
        const float4 a4 = *(const float4*)(A + (size_t)(m0 + aRow) * K + kt + aK);
        const float4 b4 = *(const float4*)(B + (size_t)(kt + bRow) * N + n0 + bC);
        __syncthreads();
        As[aK + 0][aRow] = a4.x;
        As[aK + 1][aRow] = a4.y;
        As[aK + 2][aRow] = a4.z;
        As[aK + 3][aRow] = a4.w;
        *(float4*)&Bs[bRow][bC] = b4;
        __syncthreads();
#pragma unroll
        for (int kk = 0; kk < 16; kk++) {
            const float4 av = *(const float4*)&As[kk][rm];
            const float4 bv = *(const float4*)&Bs[kk][cn];
            const float a_[4] = {av.x, av.y, av.z, av.w};
            const float b_[4] = {bv.x, bv.y, bv.z, bv.w};
#pragma unroll
            for (int i = 0; i < 4; i++)
#pragma unroll
                for (int j = 0; j < 4; j++) acc[i][j] += a_[i] * b_[j];
        }
    }

#pragma unroll
    for (int i = 0; i < 4; i++) {
        const int row = m0 + rm + i;
        float4 o;
        float cvals[4];
#pragma unroll
        for (int j = 0; j < 4; j++) {
            const int col = n0 + cn + j;
            float c = acc[i][j] + bias[col];
            if (ACT == 1) c = gelu_exact(c);
            else if (ACT == 2) c = fmaxf(c, 0.f);
            if (RES) c += res[(size_t)row * N + col];
            cvals[j] = c;
        }
        o.x = cvals[0]; o.y = cvals[1]; o.z = cvals[2]; o.w = cvals[3];
        *(float4*)(C + (size_t)row * N + n0 + cn) = o;
    }
}

// ================= Flash attention with tf32 mma.sync + ldmatrix =============
// CTA: 128 threads (4 warps). 64-query tile per CTA, warp owns 16 rows.
// smem: Qs[64][68] (pre-scaled), Ks[64][68] (aliased by P after S-phase), Vt[64][68]
#define ATT_LD 68
#define ATT_SMEM (3 * 64 * ATT_LD * 4)   // 52224 B

__global__ __launch_bounds__(128) void attn_mma(const float* __restrict__ q,
                                                const float* __restrict__ k,
                                                const float* __restrict__ v,
                                                float* __restrict__ y) {
    extern __shared__ float sm[];
    float* Qs = sm;                    // [64][68]
    float* Ks = Qs + 64 * ATT_LD;      // [64][68]; P aliases this after S phase
    float* Vt = Ks + 64 * ATT_LD;      // [64][68]  Vt[d][j] = V[j][d]

    const int bh = blockIdx.x;
    const int b = bh >> 4, h = bh & 15;
    const int qb = blockIdx.y;
    const int tid = threadIdx.x;
    const int w = tid >> 5, lane = tid & 31;
    const int g = lane >> 2, tig = lane & 3;

    // ldmatrix lane addressing
    const int a_lrow = lane & 15;            // A-frag: row within 16
    const int a_koff = (lane >> 4) * 4;      // A-frag: k half
    const int b_lrow = lane & 7;             // B-frag: row within 8
    const int b_koff = ((lane >> 3) & 1) * 4;

    const uint32_t sb   = s2u(sm);
    const uint32_t Qs_u = sb;
    const uint32_t Ks_u = sb + 64 * ATT_LD * 4;
    const uint32_t Vt_u = Ks_u + 64 * ATT_LD * 4;
    const uint32_t Pw_u = Ks_u + (uint32_t)(w * 16 * ATT_LD) * 4;

    const float* qp = q + (size_t)b * T_LEN * C_DIM + h * HDIM;
    const float* kp = k + (size_t)b * T_LEN * C_DIM + h * HDIM;
    const float* vp = v + (size_t)b * T_LEN * C_DIM + h * HDIM;

    // Load Q tile, pre-scaled by 1/sqrt(64)
    {
        const int r = tid >> 1, s0 = (tid & 1) * 32;
        const float* src = qp + (size_t)(qb * 64 + r) * C_DIM + s0;
        float* dst = Qs + r * ATT_LD + s0;
#pragma unroll
        for (int i = 0; i < 8; i++) {
            float4 t = *(const float4*)(src + i * 4);
            t.x *= 0.125f; t.y *= 0.125f; t.z *= 0.125f; t.w *= 0.125f;
            *(float4*)(dst + i * 4) = t;
        }
    }

    float of[8][4];
#pragma unroll
    for (int dc = 0; dc < 8; dc++)
#pragma unroll
        for (int t = 0; t < 4; t++) of[dc][t] = 0.f;
    float mi0 = -1e30f, mi1 = -1e30f, li0 = 0.f, li1 = 0.f;

    const int r_glob0 = qb * 64 + w * 16 + g;
    const int r_glob1 = r_glob0 + 8;

    for (int kb = 0; kb <= qb; kb++) {
        __syncthreads();
        // load K and V(T) tiles
        {
            const int r = tid >> 1, s0 = (tid & 1) * 32;
            const float* ks = kp + (size_t)(kb * 64 + r) * C_DIM + s0;
            float* kd = Ks + r * ATT_LD + s0;
#pragma unroll
            for (int i = 0; i < 8; i++)
                *(float4*)(kd + i * 4) = *(const float4*)(ks + i * 4);
            const float* vs = vp + (size_t)(kb * 64 + r) * C_DIM + s0;
#pragma unroll
            for (int i = 0; i < 8; i++) {
                float4 t = *(const float4*)(vs + i * 4);
                const int d = s0 + i * 4;
                Vt[(d + 0) * ATT_LD + r] = t.x;
                Vt[(d + 1) * ATT_LD + r] = t.y;
                Vt[(d + 2) * ATT_LD + r] = t.z;
                Vt[(d + 3) * ATT_LD + r] = t.w;
            }
        }
        __syncthreads();

        // S = Q K^T  (ldmatrix fragments)
        float sf[8][4];
#pragma unroll
        for (int nc = 0; nc < 8; nc++)
#pragma unroll
            for (int t = 0; t < 4; t++) sf[nc][t] = 0.f;
#pragma unroll
        for (int kc = 0; kc < 8; kc++) {
            uint32_t af[4];
            ldsm_x4(af, Qs_u +
                (uint32_t)((w * 16 + a_lrow) * ATT_LD + kc * 8 + a_koff) * 4);
#pragma unroll
            for (int nc = 0; nc < 8; nc++) {
                uint32_t bf[2];
                ldsm_x2(bf, Ks_u +
                    (uint32_t)((nc * 8 + b_lrow) * ATT_LD + kc * 8 + b_koff) * 4);
                mma_tf32(sf[nc], af, bf);
            }
        }

        if (kb == qb) {
#pragma unroll
            for (int nc = 0; nc < 8; nc++) {
                const int j0 = kb * 64 + nc * 8 + 2 * tig;
                if (j0 > r_glob0)     sf[nc][0] = -1e30f;
                if (j0 + 1 > r_glob0) sf[nc][1] = -1e30f;
                if (j0 > r_glob1)     sf[nc][2] = -1e30f;
                if (j0 + 1 > r_glob1) sf[nc][3] = -1e30f;
            }
        }

        // online softmax
        float ml0 = -1e30f, ml1 = -1e30f;
#pragma unroll
        for (int nc = 0; nc < 8; nc++) {
            ml0 = fmaxf(ml0, fmaxf(sf[nc][0], sf[nc][1]));
            ml1 = fmaxf(ml1, fmaxf(sf[nc][2], sf[nc][3]));
        }
        ml0 = fmaxf(ml0, __shfl_xor_sync(0xFFFFFFFF, ml0, 1));
        ml0 = fmaxf(ml0, __shfl_xor_sync(0xFFFFFFFF, ml0, 2));
        ml1 = fmaxf(ml1, __shfl_xor_sync(0xFFFFFFFF, ml1, 1));
        ml1 = fmaxf(ml1, __shfl_xor_sync(0xFFFFFFFF, ml1, 2));

        const float mn0 = fmaxf(mi0, ml0), mn1 = fmaxf(mi1, ml1);
        const float al0 = __expf(mi0 - mn0), al1 = __expf(mi1 - mn1);
        li0 *= al0; li1 *= al1;
#pragma unroll
        for (int dc = 0; dc < 8; dc++) {
            of[dc][0] *= al0; of[dc][1] *= al0;
            of[dc][2] *= al1; of[dc][3] *= al1;
        }
#pragma unroll
        for (int nc = 0; nc < 8; nc++) {
            sf[nc][0] = __expf(sf[nc][0] - mn0);
            sf[nc][1] = __expf(sf[nc][1] - mn0);
            sf[nc][2] = __expf(sf[nc][2] - mn1);
            sf[nc][3] = __expf(sf[nc][3] - mn1);
            li0 += sf[nc][0] + sf[nc][1];
            li1 += sf[nc][2] + sf[nc][3];
        }
        mi0 = mn0; mi1 = mn1;

        // all warps done reading Ks (S phase) before P overwrites it
        __syncthreads();

        // write P into warp's own 16-row slice of Ks
        float* pw = Ks + w * 16 * ATT_LD;
#pragma unroll
        for (int nc = 0; nc < 8; nc++) {
            pw[g * ATT_LD + nc * 8 + 2 * tig]           = sf[nc][0];
            pw[g * ATT_LD + nc * 8 + 2 * tig + 1]       = sf[nc][1];
            pw[(g + 8) * ATT_LD + nc * 8 + 2 * tig]     = sf[nc][2];
            pw[(g + 8) * ATT_LD + nc * 8 + 2 * tig + 1] = sf[nc][3];
        }
        __syncwarp();

        // O += P @ V  (ldmatrix fragments)
#pragma unroll
        for (int kc = 0; kc < 8; kc++) {
            uint32_t pf[4];
            ldsm_x4(pf, Pw_u + (uint32_t)(a_lrow * ATT_LD + kc * 8 + a_koff) * 4);
#pragma unroll
            for (int dc = 0; dc < 8; dc++) {
                uint32_t bf[2];
                ldsm_x2(bf, Vt_u +
                    (uint32_t)((dc * 8 + b_lrow) * ATT_LD + kc * 8 + b_koff) * 4);
                mma_tf32(of[dc], pf, bf);
            }
        }
        __syncwarp();
    }

    li0 += __shfl_xor_sync(0xFFFFFFFF, li0, 1);
    li0 += __shfl_xor_sync(0xFFFFFFFF, li0, 2);
    li1 += __shfl_xor_sync(0xFFFFFFFF, li1, 1);
    li1 += __shfl_xor_sync(0xFFFFFFFF, li1, 2);
    const float inv0 = 1.f / li0, inv1 = 1.f / li1;

    float* yp = y + ((size_t)b * T_LEN + qb * 64 + w * 16) * C_DIM + h * HDIM;
#pragma unroll
    for (int dc = 0; dc < 8; dc++) {
        const int col = dc * 8 + 2 * tig;
        *(float2*)(yp + (size_t)g * C_DIM + col) =
            make_float2(of[dc][0] * inv0, of[dc][1] * inv0);
        *(float2*)(yp + (size_t)(g + 8) * C_DIM + col) =
            make_float2(of[dc][2] * inv1, of[dc][3] * inv1);
    }
}

// ---------------- final combine: out = 2*hidden + mlp + adapter --------------
__global__ void combine_kernel(const float* __restrict__ hidden,
                               const float* __restrict__ mlp,
                               const float* __restrict__ a,
                               float* __restrict__ out, int n) {
    int i = blockIdx.x * blockDim.x + threadIdx.x;
    if (i < n) out[i] = 2.f * hidden[i] + mlp[i] + a[i];
}

// -----------------------------------------------------------------------------
extern "C" void kernel_launch(void* const* d_in, const int* in_sizes, int n_in,
                              void* d_out, int out_size) {
    const float* x     = (const float*)d_in[0];
    const float* ln1_g = (const float*)d_in[1];
    const float* ln1_b = (const float*)d_in[2];
    const float* ln2_g = (const float*)d_in[3];
    const float* ln2_b = (const float*)d_in[4];
    const float* ln3_g = (const float*)d_in[5];
    const float* ln3_b = (const float*)d_in[6];
    const float* wq = (const float*)d_in[7];   const float* bq = (const float*)d_in[8];
    const float* wk = (const float*)d_in[9];   const float* bk = (const float*)d_in[10];
    const float* wv = (const float*)d_in[11];  const float* bv = (const float*)d_in[12];
    const float* wo = (const float*)d_in[13];  const float* bo = (const float*)d_in[14];
    const float* w1 = (const float*)d_in[15];  const float* b1 = (const float*)d_in[16];
    const float* w2 = (const float*)d_in[17];  const float* b2 = (const float*)d_in[18];
    const float* wd = (const float*)d_in[19];  const float* bd = (const float*)d_in[20];
    const float* wu = (const float*)d_in[21];  const float* bu = (const float*)d_in[22];
    float* out = (float*)d_out;

    float *h, *q, *k, *v, *y, *hidden, *m, *ff, *mlp, *n3, *ad1, *a;
    cudaGetSymbolAddress((void**)&h,      g_h);
    cudaGetSymbolAddress((void**)&q,      g_q);
    cudaGetSymbolAddress((void**)&k,      g_k);
    cudaGetSymbolAddress((void**)&v,      g_v);
    cudaGetSymbolAddress((void**)&y,      g_y);
    cudaGetSymbolAddress((void**)&hidden, g_hidden);
    cudaGetSymbolAddress((void**)&m,      g_m);
    cudaGetSymbolAddress((void**)&ff,     g_ff);
    cudaGetSymbolAddress((void**)&mlp,    g_mlp);
    cudaGetSymbolAddress((void**)&n3,     g_n3);
    cudaGetSymbolAddress((void**)&ad1,    g_ad1);
    cudaGetSymbolAddress((void**)&a,      g_a);

    cudaFuncSetAttribute(qkv_gemm, cudaFuncAttributeMaxDynamicSharedMemorySize, gemm_smem<4>());
    cudaFuncSetAttribute(tc_gemm<1, false, 4>, cudaFuncAttributeMaxDynamicSharedMemorySize, gemm_smem<4>());
    cudaFuncSetAttribute(tc_gemm<0, true, 2>,  cudaFuncAttributeMaxDynamicSharedMemorySize, gemm_smem<2>());
    cudaFuncSetAttribute(tc_gemm<0, false, 2>, cudaFuncAttributeMaxDynamicSharedMemorySize, gemm_smem<2>());
    cudaFuncSetAttribute(attn_mma, cudaFuncAttributeMaxDynamicSharedMemorySize, ATT_SMEM);

    // LN1(x), LN3(x)
    ln_kernel<<<M_ROWS, 256>>>(x, ln1_g, ln1_b, h);
    ln_kernel<<<M_ROWS, 256>>>(x, ln3_g, ln3_b, n3);

    // fused QKV projection
    qkv_gemm<<<dim3(24, 32), 256, gemm_smem<4>()>>>(h, wq, wk, wv, bq, bk, bv, q, k, v);

    // Causal attention (tensor cores + ldmatrix)
    attn_mma<<<dim3(4 * NHEAD, T_LEN / 64), 128, ATT_SMEM>>>(q, k, v, y);

    // Output projection + residual -> hidden
    tc_gemm<0, true, 2><<<dim3(8, 64), 256, gemm_smem<2>()>>>(y, wo, bo, x, hidden, C_DIM, C_DIM);

    // MLP on ln2(hidden)
    ln_kernel<<<M_ROWS, 256>>>(hidden, ln2_g, ln2_b, m);
    tc_gemm<1, false, 4><<<dim3(32, 32), 256, gemm_smem<4>()>>>(m, w1, b1, nullptr, ff, FF_DIM, C_DIM);
    tc_gemm<0, false, 2><<<dim3(8, 64), 256, gemm_smem<2>()>>>(ff, w2, b2, nullptr, mlp, C_DIM, FF_DIM);

    // Adapter on ln3(x) (small; SIMT fp32)
    dim3 gCA(A_DIM / 64, M_ROWS / 64);
    sgemm_kernel<2, false><<<gCA, 256>>>(n3, wd, bd, nullptr, ad1, M_ROWS, A_DIM, C_DIM);
    dim3 gAU(C_DIM / 64, M_ROWS / 64);
    sgemm_kernel<0, false><<<gAU, 256>>>(ad1, wu, bu, nullptr, a, M_ROWS, C_DIM, A_DIM);

    // out = 2*hidden + mlp + adapter
    const int n = M_ROWS * C_DIM;
    combine_kernel<<<(n + 255) / 256, 256>>>(hidden, mlp, a, out, n);
}

// round 7
// speedup vs baseline: 3.6055x; 1.0833x over previous
#include <cuda_runtime.h>
#include <math.h>
#include <stdint.h>

// Shapes
#define M_ROWS 4096   // B*T
#define C_DIM  1024
#define FF_DIM 4096
#define A_DIM  64
#define T_LEN  1024
#define NHEAD  16
#define HDIM   64

// ---------------- scratch (device globals; no allocs allowed) ----------------
__device__ float g_h     [M_ROWS * C_DIM];
__device__ float g_q     [M_ROWS * C_DIM];
__device__ float g_k     [M_ROWS * C_DIM];
__device__ float g_v     [M_ROWS * C_DIM];
__device__ float g_y     [M_ROWS * C_DIM];
__device__ float g_hidden[M_ROWS * C_DIM];
__device__ float g_m     [M_ROWS * C_DIM];
__device__ float g_ff    [M_ROWS * FF_DIM];
__device__ float g_mlp   [M_ROWS * C_DIM];
__device__ float g_n3    [M_ROWS * C_DIM];
__device__ float g_ad1   [M_ROWS * A_DIM];
__device__ float g_a     [M_ROWS * C_DIM];

// ======================= helpers ==============================================
__device__ __forceinline__ void cp16(uint32_t dst, const void* src) {
    asm volatile("cp.async.cg.shared.global [%0], [%1], 16;"
                 :: "r"(dst), "l"(src) : "memory");
}
__device__ __forceinline__ uint32_t s2u(const void* p) {
    uint32_t a;
    asm("{ .reg .u64 t; cvta.to.shared.u64 t, %1; cvt.u32.u64 %0, t; }"
        : "=r"(a) : "l"(p));
    return a;
}
// Raw fp32 bits fed to tf32 mma: HW uses top 19 bits (RZ-equivalent).
__device__ __forceinline__ uint32_t f2tf32(float x) { return __float_as_uint(x); }

__device__ __forceinline__ void ldsm_x4(uint32_t* r, uint32_t addr) {
    asm volatile("ldmatrix.sync.aligned.m8n8.x4.shared.b16 {%0,%1,%2,%3}, [%4];"
                 : "=r"(r[0]), "=r"(r[1]), "=r"(r[2]), "=r"(r[3]) : "r"(addr));
}
__device__ __forceinline__ void ldsm_x2(uint32_t* r, uint32_t addr) {
    asm volatile("ldmatrix.sync.aligned.m8n8.x2.shared.b16 {%0,%1}, [%2];"
                 : "=r"(r[0]), "=r"(r[1]) : "r"(addr));
}

__device__ __forceinline__ void mma_tf32(float* c, const uint32_t* a, const uint32_t* b) {
    asm volatile(
        "mma.sync.aligned.m16n8k8.row.col.f32.tf32.tf32.f32 "
        "{%0,%1,%2,%3}, {%4,%5,%6,%7}, {%8,%9}, {%0,%1,%2,%3};"
        : "+f"(c[0]), "+f"(c[1]), "+f"(c[2]), "+f"(c[3])
        : "r"(a[0]), "r"(a[1]), "r"(a[2]), "r"(a[3]), "r"(b[0]), "r"(b[1]));
}
__device__ __forceinline__ float gelu_exact(float x) {
    return 0.5f * x * (1.0f + erff(x * 0.7071067811865476f));
}

// =========================== tf32 mma.sync GEMM core ==========================
#define A_LD 36
#define B_LD 132
#define B_STAGE_F (32 * B_LD)     // 4224

template <int MI>
__host__ __device__ constexpr int stage_f() { return MI * 32 * A_LD + B_STAGE_F; }
template <int MI>
__host__ __device__ constexpr int gemm_smem() { return 2 * stage_f<MI>() * 4; }

template <int ACT, bool RES, int MI>
__device__ __forceinline__ void gemm_core(
    const float* __restrict__ A, const float* __restrict__ W,
    const float* __restrict__ bias, const float* __restrict__ res,
    float* __restrict__ C, int N, int K, int m0, int n0, float* smem)
{
    const int BMv = MI * 32;
    const int A_STAGE_F = BMv * A_LD;
    const int STAGE_F = A_STAGE_F + B_STAGE_F;

    const int tid  = threadIdx.x;
    const int wid  = tid >> 5;
    const int lane = tid & 31;
    const int g    = lane >> 2;
    const int tig  = lane & 3;
    const int wm   = wid >> 2;       // 0..1
    const int wn   = wid & 3;        // 0..3

    const int a_lrow = lane & 15;
    const int a_koff = (lane >> 4) * 4;

    const uint32_t sb = s2u(smem);

    auto load_stage = [&](int s, int b) {
        const uint32_t abase = sb + (uint32_t)(b * STAGE_F) * 4;
        const uint32_t bbase = abase + A_STAGE_F * 4;
        const float* Ag = A + (size_t)m0 * K + s * 32;
        const float* Wg = W + (size_t)(s * 32) * N + n0;
#pragma unroll
        for (int i = 0; i < MI; i++) {
            int c = tid + i * 256;
            int row = c >> 3, k4 = c & 7;
            cp16(abase + row * (A_LD * 4) + k4 * 16,
                 Ag + (size_t)row * K + k4 * 4);
        }
#pragma unroll
        for (int i = 0; i < 4; i++) {
            int c = tid + i * 256;
            int kr = c >> 5, n4 = c & 31;
            cp16(bbase + kr * (B_LD * 4) + n4 * 16,
                 Wg + (size_t)kr * N + n4 * 4);
        }
        asm volatile("cp.async.commit_group;" ::: "memory");
    };

    float acc[MI][4][4];
#pragma unroll
    for (int mi = 0; mi < MI; mi++)
#pragma unroll
        for (int ni = 0; ni < 4; ni++)
#pragma unroll
            for (int t = 0; t < 4; t++) acc[mi][ni][t] = 0.f;

    const int NS = K / 32;
    load_stage(0, 0);

    for (int s = 0; s < NS; s++) {
        const int buf = s & 1;
        if (s + 1 < NS) {
            load_stage(s + 1, buf ^ 1);
            asm volatile("cp.async.wait_group 1;" ::: "memory");
        } else {
            asm volatile("cp.async.wait_group 0;" ::: "memory");
        }
        __syncthreads();

        const uint32_t As_u = sb + (uint32_t)(buf * STAGE_F) * 4;
        const float* Bs = smem + buf * STAGE_F + A_STAGE_F;

#pragma unroll
        for (int ks = 0; ks < 4; ks++) {
            uint32_t afr[MI][4];
#pragma unroll
            for (int mi = 0; mi < MI; mi++) {
                const uint32_t ad = As_u +
                    (uint32_t)((wm * (MI * 16) + mi * 16 + a_lrow) * A_LD + ks * 8 + a_koff) * 4;
                ldsm_x4(afr[mi], ad);
            }
            uint32_t bfr[4][2];
#pragma unroll
            for (int ni = 0; ni < 4; ni++) {
                const float* p = Bs + (ks * 8 + tig) * B_LD + wn * 32 + ni * 8 + g;
                bfr[ni][0] = f2tf32(p[0]);
                bfr[ni][1] = f2tf32(p[4 * B_LD]);
            }
#pragma unroll
            for (int mi = 0; mi < MI; mi++)
#pragma unroll
                for (int ni = 0; ni < 4; ni++)
                    mma_tf32(acc[mi][ni], afr[mi], bfr[ni]);
        }
        __syncthreads();
    }

#pragma unroll
    for (int mi = 0; mi < MI; mi++) {
        const int r0 = m0 + wm * (MI * 16) + mi * 16 + g;
#pragma unroll
        for (int ni = 0; ni < 4; ni++) {
            const int col = n0 + wn * 32 + ni * 8 + tig * 2;
            const float bx = bias[col], by = bias[col + 1];
#pragma unroll
            for (int hh = 0; hh < 2; hh++) {
                const int row = r0 + hh * 8;
                float cx = acc[mi][ni][hh * 2 + 0] + bx;
                float cy = acc[mi][ni][hh * 2 + 1] + by;
                if (ACT == 1) { cx = gelu_exact(cx); cy = gelu_exact(cy); }
                else if (ACT == 2) { cx = fmaxf(cx, 0.f); cy = fmaxf(cy, 0.f); }
                if (RES) {
                    cx += res[(size_t)row * N + col];
                    cy += res[(size_t)row * N + col + 1];
                }
                *(float2*)(C + (size_t)row * N + col) = make_float2(cx, cy);
            }
        }
    }
}

template <int ACT, bool RES, int MI>
__global__ __launch_bounds__(256) void tc_gemm(
    const float* __restrict__ A, const float* __restrict__ W,
    const float* __restrict__ bias, const float* __restrict__ res,
    float* __restrict__ C, int N, int K)
{
    extern __shared__ float smem[];
    gemm_core<ACT, RES, MI>(A, W, bias, res, C, N, K,
                            blockIdx.y * (MI * 32), blockIdx.x * 128, smem);
}

// fused QKV: grid.x = 24 (3 matrices x 8 col-blocks), grid.y = 32
__global__ __launch_bounds__(256) void qkv_gemm(
    const float* __restrict__ A,
    const float* __restrict__ wq, const float* __restrict__ wk, const float* __restrict__ wv,
    const float* __restrict__ bq, const float* __restrict__ bk, const float* __restrict__ bv,
    float* __restrict__ q, float* __restrict__ k, float* __restrict__ v)
{
    extern __shared__ float smem[];
    const int mat = blockIdx.x >> 3;
    const int n0  = (blockIdx.x & 7) * 128;
    const float* W = (mat == 0) ? wq : (mat == 1) ? wk : wv;
    const float* B = (mat == 0) ? bq : (mat == 1) ? bk : bv;
    float* C       = (mat == 0) ? q  : (mat == 1) ? k  : v;
    gemm_core<0, false, 4>(A, W, B, nullptr, C, C_DIM, C_DIM,
                           blockIdx.y * 128, n0, smem);
}

// ---------------- LayerNorm: one warp per row, 8 rows per CTA ----------------
__global__ __launch_bounds__(256) void ln_kernel(const float* __restrict__ x,
                                                 const float* __restrict__ g,
                                                 const float* __restrict__ b,
                                                 float* __restrict__ out) {
    const int warp = threadIdx.x >> 5, lane = threadIdx.x & 31;
    const int row = blockIdx.x * 8 + warp;
    const float4* xr = (const float4*)(x + (size_t)row * C_DIM);

    float4 v[8];
    float s = 0.f;
#pragma unroll
    for (int i = 0; i < 8; i++) {
        v[i] = xr[i * 32 + lane];
        s += v[i].x + v[i].y + v[i].z + v[i].w;
    }
#pragma unroll
    for (int off = 16; off > 0; off >>= 1)
        s += __shfl_xor_sync(0xFFFFFFFF, s, off);
    const float mean = s * (1.0f / 1024.0f);

    float sq = 0.f;
#pragma unroll
    for (int i = 0; i < 8; i++) {
        float dx = v[i].x - mean, dy = v[i].y - mean,
              dz = v[i].z - mean, dw = v[i].w - mean;
        sq += dx * dx + dy * dy + dz * dz + dw * dw;
    }
#pragma unroll
    for (int off = 16; off > 0; off >>= 1)
        sq += __shfl_xor_sync(0xFFFFFFFF, sq, off);
    const float inv = rsqrtf(sq * (1.0f / 1024.0f) + 1e-5f);

    float4* orow = (float4*)(out + (size_t)row * C_DIM);
    const float4* gv = (const float4*)g;
    const float4* bv = (const float4*)b;
#pragma unroll
    for (int i = 0; i < 8; i++) {
        const int c = i * 32 + lane;
        float4 gg = gv[c], bb = bv[c], o;
        o.x = (v[i].x - mean) * inv * gg.x + bb.x;
        o.y = (v[i].y - mean) * inv * gg.y + bb.y;
        o.z = (v[i].z - mean) * inv * gg.z + bb.z;
        o.w = (v[i].w - mean) * inv * gg.w + bb.w;
        orow[c] = o;
    }
}

// ------------- SIMT SGEMM (adapter path only) --------------------------------
template <int ACT, bool RES>
__global__ __launch_bounds__(256) void sgemm_kernel(
    const float* __restrict__ A, const float* __restrict__ B,
    const float* __restrict__ bias, const float* __restrict__ res,
    float* __restrict__ C, int M, int N, int K)
{
    __shared__ float As[16][64];
    __shared__ float Bs[16][64];

    const int tid = threadIdx.x;
    const int m0 = blockIdx.y * 64;
    const int n0 = blockIdx.x * 64;

    const int aRow = tid >> 2;
    const int aK   = (tid & 3) * 4;
    const int bRow = tid >> 4;
    const int bC   = (tid & 15) * 4;
    const int rm   = (tid >> 4) * 4;
    const int cn   = (tid & 15) * 4;

    float acc[4][4];
#pragma unroll
    for (int i = 0; i < 4; i++)
#pragma unroll
        for (int j = 0; j < 4; j++) acc[i][j] = 0.f;

    for (int kt = 0; kt < K; kt += 16) {
        const float4 a4 = *(const float4*)(A + (size_t)(m0 + aRow) * K + kt + aK);
        const float4 b4 = *(const float4*)(B + (size_t)(kt + bRow) * N + n0 + bC);
        __syncthreads();
        As[aK + 0][aRow] = a4.x;
        As[aK + 1][aRow] = a4.y;
        As[aK + 2][aRow] = a4.z;
        As[aK + 3][aRow] = a4.w;
        *(float4*)&Bs[bRow][bC] = b4;
        __syncthreads();
#pragma unroll
        for (int kk = 0; kk < 16; kk++) {
            const float4 av = *(const float4*)&As[kk][rm];
            const float4 bv = *(const float4*)&Bs[kk][cn];
            const float a_[4] = {av.x, av.y, av.z, av.w};
            const float b_[4] = {bv.x, bv.y, bv.z, bv.w};
#pragma unroll
            for (int i = 0; i < 4; i++)
#pragma unroll
                for (int j = 0; j < 4; j++) acc[i][j] += a_[i] * b_[j];
        }
    }

#pragma unroll
    for (int i = 0; i < 4; i++) {
        const int row = m0 + rm + i;
        float4 o;
        float cvals[4];
#pragma unroll
        for (int j = 0; j < 4; j++) {
            const int col = n0 + cn + j;
            float c = acc[i][j] + bias[col];
            if (ACT == 1) c = gelu_exact(c);
            else if (ACT == 2) c = fmaxf(c, 0.f);
            if (RES) c += res[(size_t)row * N + col];
            cvals[j] = c;
        }
        o.x = cvals[0]; o.y = cvals[1]; o.z = cvals[2]; o.w = cvals[3];
        *(float4*)(C + (size_t)row * N + n0 + cn) = o;
    }
}

// ================= Flash attention: 128-query tile, 32 rows/warp =============
// CTA: 128 threads (4 warps). Warp owns 32 query rows (2 m16 tiles) so each
// B-fragment (K/V) load feeds two MMAs. P has its own buffer (no aliasing).
#define ATT_LD 68
#define ATT_QT 128
#define ATT_SMEM ((ATT_QT + 64 + 64 + ATT_QT) * ATT_LD * 4)   // 104448 B

__global__ __launch_bounds__(128) void attn_mma(const float* __restrict__ q,
                                                const float* __restrict__ k,
                                                const float* __restrict__ v,
                                                float* __restrict__ y) {
    extern __shared__ float sm[];
    float* Qs = sm;                        // [128][68]
    float* Ks = Qs + ATT_QT * ATT_LD;      // [64][68]
    float* Vt = Ks + 64 * ATT_LD;          // [64][68]  Vt[d][j] = V[j][d]
    float* Ps = Vt + 64 * ATT_LD;          // [128][68]

    const int bh = blockIdx.x;
    const int b = bh >> 4, h = bh & 15;
    const int qb = (gridDim.y - 1) - blockIdx.y;   // heavy tiles first
    const int q0 = qb * ATT_QT;
    const int tid = threadIdx.x;
    const int w = tid >> 5, lane = tid & 31;
    const int g = lane >> 2, tig = lane & 3;

    const int a_lrow = lane & 15;
    const int a_koff = (lane >> 4) * 4;
    const int b_lrow = lane & 7;
    const int b_koff = ((lane >> 3) & 1) * 4;

    const uint32_t sb   = s2u(sm);
    const uint32_t Qs_u = sb;
    const uint32_t Ks_u = sb + (uint32_t)(ATT_QT * ATT_LD) * 4;
    const uint32_t Vt_u = Ks_u + (uint32_t)(64 * ATT_LD) * 4;
    const uint32_t Ps_u = Vt_u + (uint32_t)(64 * ATT_LD) * 4;

    const float* qp = q + (size_t)b * T_LEN * C_DIM + h * HDIM;
    const float* kp = k + (size_t)b * T_LEN * C_DIM + h * HDIM;
    const float* vp = v + (size_t)b * T_LEN * C_DIM + h * HDIM;

    // Load Q tile (128 rows), pre-scaled by 1/sqrt(64). One row per thread.
    {
        const float* src = qp + (size_t)(q0 + tid) * C_DIM;
        float* dst = Qs + tid * ATT_LD;
#pragma unroll
        for (int i = 0; i < 16; i++) {
            float4 t = *(const float4*)(src + i * 4);
            t.x *= 0.125f; t.y *= 0.125f; t.z *= 0.125f; t.w *= 0.125f;
            *(float4*)(dst + i * 4) = t;
        }
    }

    float of[2][8][4];
#pragma unroll
    for (int mi = 0; mi < 2; mi++)
#pragma unroll
        for (int dc = 0; dc < 8; dc++)
#pragma unroll
            for (int t = 0; t < 4; t++) of[mi][dc][t] = 0.f;
    float mrow[2][2] = {{-1e30f, -1e30f}, {-1e30f, -1e30f}};
    float lrow[2][2] = {{0.f, 0.f}, {0.f, 0.f}};

    const int kb_max = 2 * qb + 1;
    const int wmaxrow = q0 + w * 32 + 31;

    for (int kb = 0; kb <= kb_max; kb++) {
        __syncthreads();
        // load K and V(T) tiles (64 key rows)
        {
            const int r = tid >> 1, s0 = (tid & 1) * 32;
            const float* ks = kp + (size_t)(kb * 64 + r) * C_DIM + s0;
            float* kd = Ks + r * ATT_LD + s0;
#pragma unroll
            for (int i = 0; i < 8; i++)
                *(float4*)(kd + i * 4) = *(const float4*)(ks + i * 4);
            const float* vs = vp + (size_t)(kb * 64 + r) * C_DIM + s0;
#pragma unroll
            for (int i = 0; i < 8; i++) {
                float4 t = *(const float4*)(vs + i * 4);
                const int d = s0 + i * 4;
                Vt[(d + 0) * ATT_LD + r] = t.x;
                Vt[(d + 1) * ATT_LD + r] = t.y;
                Vt[(d + 2) * ATT_LD + r] = t.z;
                Vt[(d + 3) * ATT_LD + r] = t.w;
            }
        }
        __syncthreads();

        if (kb * 64 > wmaxrow) continue;   // fully-masked for this warp

        // S = Q K^T : two 16-row tiles share every B fragment
        float sf[2][8][4];
#pragma unroll
        for (int mi = 0; mi < 2; mi++)
#pragma unroll
            for (int nc = 0; nc < 8; nc++)
#pragma unroll
                for (int t = 0; t < 4; t++) sf[mi][nc][t] = 0.f;
#pragma unroll
        for (int kc = 0; kc < 8; kc++) {
            uint32_t af[2][4];
            ldsm_x4(af[0], Qs_u +
                (uint32_t)((w * 32 + a_lrow) * ATT_LD + kc * 8 + a_koff) * 4);
            ldsm_x4(af[1], Qs_u +
                (uint32_t)((w * 32 + 16 + a_lrow) * ATT_LD + kc * 8 + a_koff) * 4);
#pragma unroll
            for (int nc = 0; nc < 8; nc++) {
                uint32_t bf[2];
                ldsm_x2(bf, Ks_u +
                    (uint32_t)((nc * 8 + b_lrow) * ATT_LD + kc * 8 + b_koff) * 4);
                mma_tf32(sf[0][nc], af[0], bf);
                mma_tf32(sf[1][nc], af[1], bf);
            }
        }

        // causal mask + online softmax per 16-row tile
#pragma unroll
        for (int mi = 0; mi < 2; mi++) {
            const int base = q0 + w * 32 + mi * 16;
            if (kb * 64 + 63 > base) {
                const int r0 = base + g, r1 = base + g + 8;
#pragma unroll
                for (int nc = 0; nc < 8; nc++) {
                    const int j0 = kb * 64 + nc * 8 + 2 * tig;
                    if (j0 > r0)     sf[mi][nc][0] = -1e30f;
                    if (j0 + 1 > r0) sf[mi][nc][1] = -1e30f;
                    if (j0 > r1)     sf[mi][nc][2] = -1e30f;
                    if (j0 + 1 > r1) sf[mi][nc][3] = -1e30f;
                }
            }
            float ml0 = -1e30f, ml1 = -1e30f;
#pragma unroll
            for (int nc = 0; nc < 8; nc++) {
                ml0 = fmaxf(ml0, fmaxf(sf[mi][nc][0], sf[mi][nc][1]));
                ml1 = fmaxf(ml1, fmaxf(sf[mi][nc][2], sf[mi][nc][3]));
            }
            ml0 = fmaxf(ml0, __shfl_xor_sync(0xFFFFFFFF, ml0, 1));
            ml0 = fmaxf(ml0, __shfl_xor_sync(0xFFFFFFFF, ml0, 2));
            ml1 = fmaxf(ml1, __shfl_xor_sync(0xFFFFFFFF, ml1, 1));
            ml1 = fmaxf(ml1, __shfl_xor_sync(0xFFFFFFFF, ml1, 2));

            const float mn0 = fmaxf(mrow[mi][0], ml0);
            const float mn1 = fmaxf(mrow[mi][1], ml1);
            const float al0 = __expf(mrow[mi][0] - mn0);
            const float al1 = __expf(mrow[mi][1] - mn1);
            lrow[mi][0] *= al0; lrow[mi][1] *= al1;
#pragma unroll
            for (int dc = 0; dc < 8; dc++) {
                of[mi][dc][0] *= al0; of[mi][dc][1] *= al0;
                of[mi][dc][2] *= al1; of[mi][dc][3] *= al1;
            }
#pragma unroll
            for (int nc = 0; nc < 8; nc++) {
                sf[mi][nc][0] = __expf(sf[mi][nc][0] - mn0);
                sf[mi][nc][1] = __expf(sf[mi][nc][1] - mn0);
                sf[mi][nc][2] = __expf(sf[mi][nc][2] - mn1);
                sf[mi][nc][3] = __expf(sf[mi][nc][3] - mn1);
                lrow[mi][0] += sf[mi][nc][0] + sf[mi][nc][1];
                lrow[mi][1] += sf[mi][nc][2] + sf[mi][nc][3];
            }
            mrow[mi][0] = mn0; mrow[mi][1] = mn1;

            // write P tile (warp-private rows)
            float* pw = Ps + (w * 32 + mi * 16) * ATT_LD;
#pragma unroll
            for (int nc = 0; nc < 8; nc++) {
                pw[g * ATT_LD + nc * 8 + 2 * tig]           = sf[mi][nc][0];
                pw[g * ATT_LD + nc * 8 + 2 * tig + 1]       = sf[mi][nc][1];
                pw[(g + 8) * ATT_LD + nc * 8 + 2 * tig]     = sf[mi][nc][2];
                pw[(g + 8) * ATT_LD + nc * 8 + 2 * tig + 1] = sf[mi][nc][3];
            }
        }
        __syncwarp();

        // O += P @ V : two P tiles share every V fragment
#pragma unroll
        for (int kc = 0; kc < 8; kc++) {
            uint32_t pf[2][4];
            ldsm_x4(pf[0], Ps_u +
                (uint32_t)((w * 32 + a_lrow) * ATT_LD + kc * 8 + a_koff) * 4);
            ldsm_x4(pf[1], Ps_u +
                (uint32_t)((w * 32 + 16 + a_lrow) * ATT_LD + kc * 8 + a_koff) * 4);
#pragma unroll
            for (int dc = 0; dc < 8; dc++) {
                uint32_t bf[2];
                ldsm_x2(bf, Vt_u +
                    (uint32_t)((dc * 8 + b_lrow) * ATT_LD + kc * 8 + b_koff) * 4);
                mma_tf32(of[0][dc], pf[0], bf);
                mma_tf32(of[1][dc], pf[1], bf);
            }
        }
        __syncwarp();
    }

    // finalize
#pragma unroll
    for (int mi = 0; mi < 2; mi++) {
        float l0 = lrow[mi][0], l1 = lrow[mi][1];
        l0 += __shfl_xor_sync(0xFFFFFFFF, l0, 1);
        l0 += __shfl_xor_sync(0xFFFFFFFF, l0, 2);
        l1 += __shfl_xor_sync(0xFFFFFFFF, l1, 1);
        l1 += __shfl_xor_sync(0xFFFFFFFF, l1, 2);
        const float inv0 = 1.f / l0, inv1 = 1.f / l1;

        float* yp = y + ((size_t)b * T_LEN + q0 + w * 32 + mi * 16) * C_DIM + h * HDIM;
#pragma unroll
        for (int dc = 0; dc < 8; dc++) {
            const int col = dc * 8 + 2 * tig;
            *(float2*)(yp + (size_t)g * C_DIM + col) =
                make_float2(of[mi][dc][0] * inv0, of[mi][dc][1] * inv0);
            *(float2*)(yp + (size_t)(g + 8) * C_DIM + col) =
                make_float2(of[mi][dc][2] * inv1, of[mi][dc][3] * inv1);
        }
    }
}

// ---------------- final combine: out = 2*hidden + mlp + adapter --------------
__global__ void combine_kernel(const float* __restrict__ hidden,
                               const float* __restrict__ mlp,
                               const float* __restrict__ a,
                               float* __restrict__ out, int n) {
    int i = blockIdx.x * blockDim.x + threadIdx.x;
    if (i < n) out[i] = 2.f * hidden[i] + mlp[i] + a[i];
}

// -----------------------------------------------------------------------------
extern "C" void kernel_launch(void* const* d_in, const int* in_sizes, int n_in,
                              void* d_out, int out_size) {
    const float* x     = (const float*)d_in[0];
    const float* ln1_g = (const float*)d_in[1];
    const float* ln1_b = (const float*)d_in[2];
    const float* ln2_g = (const float*)d_in[3];
    const float* ln2_b = (const float*)d_in[4];
    const float* ln3_g = (const float*)d_in[5];
    const float* ln3_b = (const float*)d_in[6];
    const float* wq = (const float*)d_in[7];   const float* bq = (const float*)d_in[8];
    const float* wk = (const float*)d_in[9];   const float* bk = (const float*)d_in[10];
    const float* wv = (const float*)d_in[11];  const float* bv = (const float*)d_in[12];
    const float* wo = (const float*)d_in[13];  const float* bo = (const float*)d_in[14];
    const float* w1 = (const float*)d_in[15];  const float* b1 = (const float*)d_in[16];
    const float* w2 = (const float*)d_in[17];  const float* b2 = (const float*)d_in[18];
    const float* wd = (const float*)d_in[19];  const float* bd = (const float*)d_in[20];
    const float* wu = (const float*)d_in[21];  const float* bu = (const float*)d_in[22];
    float* out = (float*)d_out;

    float *h, *q, *k, *v, *y, *hidden, *m, *ff, *mlp, *n3, *ad1, *a;
    cudaGetSymbolAddress((void**)&h,      g_h);
    cudaGetSymbolAddress((void**)&q,      g_q);
    cudaGetSymbolAddress((void**)&k,      g_k);
    cudaGetSymbolAddress((void**)&v,      g_v);
    cudaGetSymbolAddress((void**)&y,      g_y);
    cudaGetSymbolAddress((void**)&hidden, g_hidden);
    cudaGetSymbolAddress((void**)&m,      g_m);
    cudaGetSymbolAddress((void**)&ff,     g_ff);
    cudaGetSymbolAddress((void**)&mlp,    g_mlp);
    cudaGetSymbolAddress((void**)&n3,     g_n3);
    cudaGetSymbolAddress((void**)&ad1,    g_ad1);
    cudaGetSymbolAddress((void**)&a,      g_a);

    cudaFuncSetAttribute(qkv_gemm, cudaFuncAttributeMaxDynamicSharedMemorySize, gemm_smem<4>());
    cudaFuncSetAttribute(tc_gemm<1, false, 4>, cudaFuncAttributeMaxDynamicSharedMemorySize, gemm_smem<4>());
    cudaFuncSetAttribute(tc_gemm<0, true, 2>,  cudaFuncAttributeMaxDynamicSharedMemorySize, gemm_smem<2>());
    cudaFuncSetAttribute(tc_gemm<0, false, 2>, cudaFuncAttributeMaxDynamicSharedMemorySize, gemm_smem<2>());
    cudaFuncSetAttribute(attn_mma, cudaFuncAttributeMaxDynamicSharedMemorySize, ATT_SMEM);

    // LN1(x), LN3(x)
    ln_kernel<<<M_ROWS / 8, 256>>>(x, ln1_g, ln1_b, h);
    ln_kernel<<<M_ROWS / 8, 256>>>(x, ln3_g, ln3_b, n3);

    // fused QKV projection
    qkv_gemm<<<dim3(24, 32), 256, gemm_smem<4>()>>>(h, wq, wk, wv, bq, bk, bv, q, k, v);

    // Causal attention (tensor cores, 128-query tiles)
    attn_mma<<<dim3(4 * NHEAD, T_LEN / ATT_QT), 128, ATT_SMEM>>>(q, k, v, y);

    // Output projection + residual -> hidden
    tc_gemm<0, true, 2><<<dim3(8, 64), 256, gemm_smem<2>()>>>(y, wo, bo, x, hidden, C_DIM, C_DIM);

    // MLP on ln2(hidden)
    ln_kernel<<<M_ROWS / 8, 256>>>(hidden, ln2_g, ln2_b, m);
    tc_gemm<1, false, 4><<<dim3(32, 32), 256, gemm_smem<4>()>>>(m, w1, b1, nullptr, ff, FF_DIM, C_DIM);
    tc_gemm<0, false, 2><<<dim3(8, 64), 256, gemm_smem<2>()>>>(ff, w2, b2, nullptr, mlp, C_DIM, FF_DIM);

    // Adapter on ln3(x) (small; SIMT fp32)
    dim3 gCA(A_DIM / 64, M_ROWS / 64);
    sgemm_kernel<2, false><<<gCA, 256>>>(n3, wd, bd, nullptr, ad1, M_ROWS, A_DIM, C_DIM);
    dim3 gAU(C_DIM / 64, M_ROWS / 64);
    sgemm_kernel<0, false><<<gAU, 256>>>(ad1, wu, bu, nullptr, a, M_ROWS, C_DIM, A_DIM);

    // out = 2*hidden + mlp + adapter
    const int n = M_ROWS * C_DIM;
    combine_kernel<<<(n + 255) / 256, 256>>>(hidden, mlp, a, out, n);
}

// round 9
// speedup vs baseline: 3.8299x; 1.0622x over previous
#include <cuda_runtime.h>
#include <math.h>
#include <stdint.h>

// Shapes
#define M_ROWS 4096   // B*T
#define C_DIM  1024
#define FF_DIM 4096
#define A_DIM  64
#define T_LEN  1024
#define NHEAD  16
#define HDIM   64

// ---------------- scratch (device globals; no allocs allowed) ----------------
__device__ float g_h     [M_ROWS * C_DIM];
__device__ float g_q     [M_ROWS * C_DIM];
__device__ float g_k     [M_ROWS * C_DIM];
__device__ float g_v     [M_ROWS * C_DIM];
__device__ float g_y     [M_ROWS * C_DIM];
__device__ float g_hidden[M_ROWS * C_DIM];
__device__ float g_m     [M_ROWS * C_DIM];
__device__ float g_ff    [M_ROWS * FF_DIM];
__device__ float g_mlp   [M_ROWS * C_DIM];
__device__ float g_n3    [M_ROWS * C_DIM];
__device__ float g_ad1   [M_ROWS * A_DIM];

// ======================= helpers ==============================================
__device__ __forceinline__ void cp16(uint32_t dst, const void* src) {
    asm volatile("cp.async.cg.shared.global [%0], [%1], 16;"
                 :: "r"(dst), "l"(src) : "memory");
}
__device__ __forceinline__ uint32_t s2u(const void* p) {
    uint32_t a;
    asm("{ .reg .u64 t; cvta.to.shared.u64 t, %1; cvt.u32.u64 %0, t; }"
        : "=r"(a) : "l"(p));
    return a;
}
// Raw fp32 bits fed to tf32 mma: HW uses top 19 bits (RZ-equivalent).
__device__ __forceinline__ uint32_t f2tf32(float x) { return __float_as_uint(x); }

__device__ __forceinline__ void ldsm_x4(uint32_t* r, uint32_t addr) {
    asm volatile("ldmatrix.sync.aligned.m8n8.x4.shared.b16 {%0,%1,%2,%3}, [%4];"
                 : "=r"(r[0]), "=r"(r[1]), "=r"(r[2]), "=r"(r[3]) : "r"(addr));
}

__device__ __forceinline__ void mma_tf32(float* c, const uint32_t* a, const uint32_t* b) {
    asm volatile(
        "mma.sync.aligned.m16n8k8.row.col.f32.tf32.tf32.f32 "
        "{%0,%1,%2,%3}, {%4,%5,%6,%7}, {%8,%9}, {%0,%1,%2,%3};"
        : "+f"(c[0]), "+f"(c[1]), "+f"(c[2]), "+f"(c[3])
        : "r"(a[0]), "r"(a[1]), "r"(a[2]), "r"(a[3]), "r"(b[0]), "r"(b[1]));
}
__device__ __forceinline__ float gelu_exact(float x) {
    return 0.5f * x * (1.0f + erff(x * 0.7071067811865476f));
}

// =========================== tf32 mma.sync GEMM core ==========================
#define A_LD 36
#define B_LD 132
#define B_STAGE_F (32 * B_LD)     // 4224

template <int MI>
__host__ __device__ constexpr int stage_f() { return MI * 32 * A_LD + B_STAGE_F; }
template <int MI>
__host__ __device__ constexpr int gemm_smem() { return 2 * stage_f<MI>() * 4; }

// RMODE: 0 none, 1 out += res1, 2 out += 2*res1 + res2 (final combine)
template <int ACT, int RMODE, int MI>
__device__ __forceinline__ void gemm_core(
    const float* __restrict__ A, const float* __restrict__ W,
    const float* __restrict__ bias,
    const float* __restrict__ res1, const float* __restrict__ res2,
    float* __restrict__ C, int N, int K, int m0, int n0, float* smem)
{
    const int BMv = MI * 32;
    const int A_STAGE_F = BMv * A_LD;
    const int STAGE_F = A_STAGE_F + B_STAGE_F;

    const int tid  = threadIdx.x;
    const int wid  = tid >> 5;
    const int lane = tid & 31;
    const int g    = lane >> 2;
    const int tig  = lane & 3;
    const int wm   = wid >> 2;       // 0..1
    const int wn   = wid & 3;        // 0..3

    const int a_lrow = lane & 15;
    const int a_koff = (lane >> 4) * 4;

    const uint32_t sb = s2u(smem);

    auto load_stage = [&](int s, int b) {
        const uint32_t abase = sb + (uint32_t)(b * STAGE_F) * 4;
        const uint32_t bbase = abase + A_STAGE_F * 4;
        const float* Ag = A + (size_t)m0 * K + s * 32;
        const float* Wg = W + (size_t)(s * 32) * N + n0;
#pragma unroll
        for (int i = 0; i < MI; i++) {
            int c = tid + i * 256;
            int row = c >> 3, k4 = c & 7;
            cp16(abase + row * (A_LD * 4) + k4 * 16,
                 Ag + (size_t)row * K + k4 * 4);
        }
#pragma unroll
        for (int i = 0; i < 4; i++) {
            int c = tid + i * 256;
            int kr = c >> 5, n4 = c & 31;
            cp16(bbase + kr * (B_LD * 4) + n4 * 16,
                 Wg + (size_t)kr * N + n4 * 4);
        }
        asm volatile("cp.async.commit_group;" ::: "memory");
    };

    float acc[MI][4][4];
#pragma unroll
    for (int mi = 0; mi < MI; mi++)
#pragma unroll
        for (int ni = 0; ni < 4; ni++)
#pragma unroll
            for (int t = 0; t < 4; t++) acc[mi][ni][t] = 0.f;

    const int NS = K / 32;
    load_stage(0, 0);

    for (int s = 0; s < NS; s++) {
        const int buf = s & 1;
        if (s + 1 < NS) {
            load_stage(s + 1, buf ^ 1);
            asm volatile("cp.async.wait_group 1;" ::: "memory");
        } else {
            asm volatile("cp.async.wait_group 0;" ::: "memory");
        }
        __syncthreads();

        const uint32_t As_u = sb + (uint32_t)(buf * STAGE_F) * 4;
        const float* Bs = smem + buf * STAGE_F + A_STAGE_F;

#pragma unroll
        for (int ks = 0; ks < 4; ks++) {
            uint32_t afr[MI][4];
#pragma unroll
            for (int mi = 0; mi < MI; mi++) {
                const uint32_t ad = As_u +
                    (uint32_t)((wm * (MI * 16) + mi * 16 + a_lrow) * A_LD + ks * 8 + a_koff) * 4;
                ldsm_x4(afr[mi], ad);
            }
            uint32_t bfr[4][2];
#pragma unroll
            for (int ni = 0; ni < 4; ni++) {
                const float* p = Bs + (ks * 8 + tig) * B_LD + wn * 32 + ni * 8 + g;
                bfr[ni][0] = f2tf32(p[0]);
                bfr[ni][1] = f2tf32(p[4 * B_LD]);
            }
#pragma unroll
            for (int mi = 0; mi < MI; mi++)
#pragma unroll
                for (int ni = 0; ni < 4; ni++)
                    mma_tf32(acc[mi][ni], afr[mi], bfr[ni]);
        }
        __syncthreads();
    }

#pragma unroll
    for (int mi = 0; mi < MI; mi++) {
        const int r0 = m0 + wm * (MI * 16) + mi * 16 + g;
#pragma unroll
        for (int ni = 0; ni < 4; ni++) {
            const int col = n0 + wn * 32 + ni * 8 + tig * 2;
            const float bx = bias[col], by = bias[col + 1];
#pragma unroll
            for (int hh = 0; hh < 2; hh++) {
                const int row = r0 + hh * 8;
                float cx = acc[mi][ni][hh * 2 + 0] + bx;
                float cy = acc[mi][ni][hh * 2 + 1] + by;
                if (ACT == 1) { cx = gelu_exact(cx); cy = gelu_exact(cy); }
                else if (ACT == 2) { cx = fmaxf(cx, 0.f); cy = fmaxf(cy, 0.f); }
                if (RMODE == 1) {
                    cx += res1[(size_t)row * N + col];
                    cy += res1[(size_t)row * N + col + 1];
                } else if (RMODE == 2) {
                    const float2 h2 = *(const float2*)(res1 + (size_t)row * N + col);
                    const float2 m2 = *(const float2*)(res2 + (size_t)row * N + col);
                    cx += 2.f * h2.x + m2.x;
                    cy += 2.f * h2.y + m2.y;
                }
                *(float2*)(C + (size_t)row * N + col) = make_float2(cx, cy);
            }
        }
    }
}

template <int ACT, int RMODE, int MI>
__global__ __launch_bounds__(256) void tc_gemm(
    const float* __restrict__ A, const float* __restrict__ W,
    const float* __restrict__ bias,
    const float* __restrict__ res1, const float* __restrict__ res2,
    float* __restrict__ C, int N, int K)
{
    extern __shared__ float smem[];
    gemm_core<ACT, RMODE, MI>(A, W, bias, res1, res2, C, N, K,
                              blockIdx.y * (MI * 32), blockIdx.x * 128, smem);
}

// fused QKV: grid.x = 24 (3 matrices x 8 col-blocks), grid.y = 32
__global__ __launch_bounds__(256) void qkv_gemm(
    const float* __restrict__ A,
    const float* __restrict__ wq, const float* __restrict__ wk, const float* __restrict__ wv,
    const float* __restrict__ bq, const float* __restrict__ bk, const float* __restrict__ bv,
    float* __restrict__ q, float* __restrict__ k, float* __restrict__ v)
{
    extern __shared__ float smem[];
    const int mat = blockIdx.x >> 3;
    const int n0  = (blockIdx.x & 7) * 128;
    const float* W = (mat == 0) ? wq : (mat == 1) ? wk : wv;
    const float* B = (mat == 0) ? bq : (mat == 1) ? bk : bv;
    float* C       = (mat == 0) ? q  : (mat == 1) ? k  : v;
    gemm_core<0, 0, 4>(A, W, B, nullptr, nullptr, C, C_DIM, C_DIM,
                       blockIdx.y * 128, n0, smem);
}

// ============== adapter-down GEMM: N=64, relu, tensor cores ==================
// CTA 256 thr = 8 warps (4m x 2n). Tile 128m x 64n, K staged by 32.
#define AD_B_LD 68
#define AD_STAGE_F (128 * A_LD + 32 * AD_B_LD)   // 4608 + 2176 = 6784
#define AD_SMEM (2 * AD_STAGE_F * 4)             // 54272

__global__ __launch_bounds__(256) void adapter_down(
    const float* __restrict__ A, const float* __restrict__ W,
    const float* __restrict__ bias, float* __restrict__ C, int K)
{
    extern __shared__ float smem[];
    const int tid  = threadIdx.x;
    const int wid  = tid >> 5;
    const int lane = tid & 31;
    const int g    = lane >> 2;
    const int tig  = lane & 3;
    const int wm   = wid >> 1;       // 0..3
    const int wn   = wid & 1;        // 0..1
    const int m0   = blockIdx.x * 128;

    const int a_lrow = lane & 15;
    const int a_koff = (lane >> 4) * 4;

    const uint32_t sb = s2u(smem);

    auto load_stage = [&](int s, int b) {
        const uint32_t abase = sb + (uint32_t)(b * AD_STAGE_F) * 4;
        const uint32_t bbase = abase + 128 * A_LD * 4;
        const float* Ag = A + (size_t)m0 * K + s * 32;
        const float* Wg = W + (size_t)(s * 32) * A_DIM;
#pragma unroll
        for (int i = 0; i < 4; i++) {
            int c = tid + i * 256;
            int row = c >> 3, k4 = c & 7;
            cp16(abase + row * (A_LD * 4) + k4 * 16,
                 Ag + (size_t)row * K + k4 * 4);
        }
        // B: 32 k-rows x 16 chunks = 512 chunks; 2 per thread (BUGFIX from R8)
#pragma unroll
        for (int i = 0; i < 2; i++) {
            int c = tid + i * 256;
            int kr = c >> 4, n4 = c & 15;
            cp16(bbase + kr * (AD_B_LD * 4) + n4 * 16,
                 Wg + (size_t)kr * A_DIM + n4 * 4);
        }
        asm volatile("cp.async.commit_group;" ::: "memory");
    };

    float acc[2][4][4];
#pragma unroll
    for (int mi = 0; mi < 2; mi++)
#pragma unroll
        for (int ni = 0; ni < 4; ni++)
#pragma unroll
            for (int t = 0; t < 4; t++) acc[mi][ni][t] = 0.f;

    const int NS = K / 32;
    load_stage(0, 0);

    for (int s = 0; s < NS; s++) {
        const int buf = s & 1;
        if (s + 1 < NS) {
            load_stage(s + 1, buf ^ 1);
            asm volatile("cp.async.wait_group 1;" ::: "memory");
        } else {
            asm volatile("cp.async.wait_group 0;" ::: "memory");
        }
        __syncthreads();

        const uint32_t As_u = sb + (uint32_t)(buf * AD_STAGE_F) * 4;
        const float* Bs = smem + buf * AD_STAGE_F + 128 * A_LD;

#pragma unroll
        for (int ks = 0; ks < 4; ks++) {
            uint32_t afr[2][4];
#pragma unroll
            for (int mi = 0; mi < 2; mi++) {
                ldsm_x4(afr[mi], As_u +
                    (uint32_t)((wm * 32 + mi * 16 + a_lrow) * A_LD + ks * 8 + a_koff) * 4);
            }
            uint32_t bfr[4][2];
#pragma unroll
            for (int ni = 0; ni < 4; ni++) {
                const float* p = Bs + (ks * 8 + tig) * AD_B_LD + wn * 32 + ni * 8 + g;
                bfr[ni][0] = f2tf32(p[0]);
                bfr[ni][1] = f2tf32(p[4 * AD_B_LD]);
            }
#pragma unroll
            for (int mi = 0; mi < 2; mi++)
#pragma unroll
                for (int ni = 0; ni < 4; ni++)
                    mma_tf32(acc[mi][ni], afr[mi], bfr[ni]);
        }
        __syncthreads();
    }

#pragma unroll
    for (int mi = 0; mi < 2; mi++) {
        const int r0 = m0 + wm * 32 + mi * 16 + g;
#pragma unroll
        for (int ni = 0; ni < 4; ni++) {
            const int col = wn * 32 + ni * 8 + tig * 2;
            const float bx = bias[col], by = bias[col + 1];
#pragma unroll
            for (int hh = 0; hh < 2; hh++) {
                const int row = r0 + hh * 8;
                float cx = fmaxf(acc[mi][ni][hh * 2 + 0] + bx, 0.f);
                float cy = fmaxf(acc[mi][ni][hh * 2 + 1] + by, 0.f);
                *(float2*)(C + (size_t)row * A_DIM + col) = make_float2(cx, cy);
            }
        }
    }
}

// ---------------- LayerNorm: one warp per row, 8 rows per CTA ----------------
__global__ __launch_bounds__(256) void ln_kernel(const float* __restrict__ x,
                                                 const float* __restrict__ g,
                                                 const float* __restrict__ b,
                                                 float* __restrict__ out) {
    const int warp = threadIdx.x >> 5, lane = threadIdx.x & 31;
    const int row = blockIdx.x * 8 + warp;
    const float4* xr = (const float4*)(x + (size_t)row * C_DIM);

    float4 v[8];
    float s = 0.f;
#pragma unroll
    for (int i = 0; i < 8; i++) {
        v[i] = xr[i * 32 + lane];
        s += v[i].x + v[i].y + v[i].z + v[i].w;
    }
#pragma unroll
    for (int off = 16; off > 0; off >>= 1)
        s += __shfl_xor_sync(0xFFFFFFFF, s, off);
    const float mean = s * (1.0f / 1024.0f);

    float sq = 0.f;
#pragma unroll
    for (int i = 0; i < 8; i++) {
        float dx = v[i].x - mean, dy = v[i].y - mean,
              dz = v[i].z - mean, dw = v[i].w - mean;
        sq += dx * dx + dy * dy + dz * dz + dw * dw;
    }
#pragma unroll
    for (int off = 16; off > 0; off >>= 1)
        sq += __shfl_xor_sync(0xFFFFFFFF, sq, off);
    const float inv = rsqrtf(sq * (1.0f / 1024.0f) + 1e-5f);

    float4* orow = (float4*)(out + (size_t)row * C_DIM);
    const float4* gv = (const float4*)g;
    const float4* bv = (const float4*)b;
#pragma unroll
    for (int i = 0; i < 8; i++) {
        const int c = i * 32 + lane;
        float4 gg = gv[c], bb = bv[c], o;
        o.x = (v[i].x - mean) * inv * gg.x + bb.x;
        o.y = (v[i].y - mean) * inv * gg.y + bb.y;
        o.z = (v[i].z - mean) * inv * gg.z + bb.z;
        o.w = (v[i].w - mean) * inv * gg.w + bb.w;
        orow[c] = o;
    }
}

// ================= Flash attention: 128-query tile, 32 rows/warp =============
#define ATT_LD 68
#define ATT_QT 128
#define ATT_SMEM ((ATT_QT + 64 + 64 + ATT_QT) * ATT_LD * 4)   // 104448 B

__global__ __launch_bounds__(128) void attn_mma(const float* __restrict__ q,
                                                const float* __restrict__ k,
                                                const float* __restrict__ v,
                                                float* __restrict__ y) {
    extern __shared__ float sm[];
    float* Qs = sm;                        // [128][68]
    float* Ks = Qs + ATT_QT * ATT_LD;      // [64][68]
    float* Vt = Ks + 64 * ATT_LD;          // [64][68]  Vt[d][j] = V[j][d]

    const int bh = blockIdx.x;
    const int b = bh >> 4, h = bh & 15;
    const int qb = (gridDim.y - 1) - blockIdx.y;   // heavy tiles first
    const int q0 = qb * ATT_QT;
    const int tid = threadIdx.x;
    const int w = tid >> 5, lane = tid & 31;
    const int g = lane >> 2, tig = lane & 3;

    const int a_lrow = lane & 15;
    const int a_koff = (lane >> 4) * 4;
    // B-frag x4 addressing: lanes 0-15 -> tile nc, 16-31 -> tile nc+1
    const int b_tile = lane >> 4;
    const int b_lrow = lane & 7;
    const int b_koff = ((lane >> 3) & 1) * 4;

    const uint32_t sb   = s2u(sm);
    const uint32_t Qs_u = sb;
    const uint32_t Ks_u = sb + (uint32_t)(ATT_QT * ATT_LD) * 4;
    const uint32_t Vt_u = Ks_u + (uint32_t)(64 * ATT_LD) * 4;
    const uint32_t Ps_u = Vt_u + (uint32_t)(64 * ATT_LD) * 4;
    float* Ps = Vt + 64 * ATT_LD;          // [128][68]

    const float* qp = q + (size_t)b * T_LEN * C_DIM + h * HDIM;
    const float* kp = k + (size_t)b * T_LEN * C_DIM + h * HDIM;
    const float* vp = v + (size_t)b * T_LEN * C_DIM + h * HDIM;

    // Load Q tile (128 rows), pre-scaled by 1/sqrt(64). One row per thread.
    {
        const float* src = qp + (size_t)(q0 + tid) * C_DIM;
        float* dst = Qs + tid * ATT_LD;
#pragma unroll
        for (int i = 0; i < 16; i++) {
            float4 t = *(const float4*)(src + i * 4);
            t.x *= 0.125f; t.y *= 0.125f; t.z *= 0.125f; t.w *= 0.125f;
            *(float4*)(dst + i * 4) = t;
        }
    }

    float of[2][8][4];
#pragma unroll
    for (int mi = 0; mi < 2; mi++)
#pragma unroll
        for (int dc = 0; dc < 8; dc++)
#pragma unroll
            for (int t = 0; t < 4; t++) of[mi][dc][t] = 0.f;
    float mrow[2][2] = {{-1e30f, -1e30f}, {-1e30f, -1e30f}};
    float lrow[2][2] = {{0.f, 0.f}, {0.f, 0.f}};

    const int kb_max = 2 * qb + 1;
    const int wmaxrow = q0 + w * 32 + 31;

    for (int kb = 0; kb <= kb_max; kb++) {
        __syncthreads();
        // load K and V(T) tiles (64 key rows)
        {
            const int r = tid >> 1, s0 = (tid & 1) * 32;
            const float* ks = kp + (size_t)(kb * 64 + r) * C_DIM + s0;
            float* kd = Ks + r * ATT_LD + s0;
#pragma unroll
            for (int i = 0; i < 8; i++)
                *(float4*)(kd + i * 4) = *(const float4*)(ks + i * 4);
            const float* vs = vp + (size_t)(kb * 64 + r) * C_DIM + s0;
#pragma unroll
            for (int i = 0; i < 8; i++) {
                float4 t = *(const float4*)(vs + i * 4);
                const int d = s0 + i * 4;
                Vt[(d + 0) * ATT_LD + r] = t.x;
                Vt[(d + 1) * ATT_LD + r] = t.y;
                Vt[(d + 2) * ATT_LD + r] = t.z;
                Vt[(d + 3) * ATT_LD + r] = t.w;
            }
        }
        __syncthreads();

        if (kb * 64 > wmaxrow) continue;   // fully-masked for this warp

        // S = Q K^T : two 16-row tiles share every B fragment (x4 = 2 n-tiles)
        float sf[2][8][4];
#pragma unroll
        for (int mi = 0; mi < 2; mi++)
#pragma unroll
            for (int nc = 0; nc < 8; nc++)
#pragma unroll
                for (int t = 0; t < 4; t++) sf[mi][nc][t] = 0.f;
#pragma unroll
        for (int kc = 0; kc < 8; kc++) {
            uint32_t af[2][4];
            ldsm_x4(af[0], Qs_u +
                (uint32_t)((w * 32 + a_lrow) * ATT_LD + kc * 8 + a_koff) * 4);
            ldsm_x4(af[1], Qs_u +
                (uint32_t)((w * 32 + 16 + a_lrow) * ATT_LD + kc * 8 + a_koff) * 4);
#pragma unroll
            for (int nc = 0; nc < 8; nc += 2) {
                uint32_t bf[4];
                ldsm_x4(bf, Ks_u +
                    (uint32_t)(((nc + b_tile) * 8 + b_lrow) * ATT_LD + kc * 8 + b_koff) * 4);
                mma_tf32(sf[0][nc],     af[0], bf);
                mma_tf32(sf[1][nc],     af[1], bf);
                mma_tf32(sf[0][nc + 1], af[0], bf + 2);
                mma_tf32(sf[1][nc + 1], af[1], bf + 2);
            }
        }

        // causal mask + online softmax per 16-row tile
#pragma unroll
        for (int mi = 0; mi < 2; mi++) {
            const int base = q0 + w * 32 + mi * 16;
            if (kb * 64 + 63 > base) {
                const int r0 = base + g, r1 = base + g + 8;
#pragma unroll
                for (int nc = 0; nc < 8; nc++) {
                    const int j0 = kb * 64 + nc * 8 + 2 * tig;
                    if (j0 > r0)     sf[mi][nc][0] = -1e30f;
                    if (j0 + 1 > r0) sf[mi][nc][1] = -1e30f;
                    if (j0 > r1)     sf[mi][nc][2] = -1e30f;
                    if (j0 + 1 > r1) sf[mi][nc][3] = -1e30f;
                }
            }
            float ml0 = -1e30f, ml1 = -1e30f;
#pragma unroll
            for (int nc = 0; nc < 8; nc++) {
                ml0 = fmaxf(ml0, fmaxf(sf[mi][nc][0], sf[mi][nc][1]));
                ml1 = fmaxf(ml1, fmaxf(sf[mi][nc][2], sf[mi][nc][3]));
            }
            ml0 = fmaxf(ml0, __shfl_xor_sync(0xFFFFFFFF, ml0, 1));
            ml0 = fmaxf(ml0, __shfl_xor_sync(0xFFFFFFFF, ml0, 2));
            ml1 = fmaxf(ml1, __shfl_xor_sync(0xFFFFFFFF, ml1, 1));
            ml1 = fmaxf(ml1, __shfl_xor_sync(0xFFFFFFFF, ml1, 2));

            const float mn0 = fmaxf(mrow[mi][0], ml0);
            const float mn1 = fmaxf(mrow[mi][1], ml1);
            const float al0 = __expf(mrow[mi][0] - mn0);
            const float al1 = __expf(mrow[mi][1] - mn1);
            lrow[mi][0] *= al0; lrow[mi][1] *= al1;
#pragma unroll
            for (int dc = 0; dc < 8; dc++) {
                of[mi][dc][0] *= al0; of[mi][dc][1] *= al0;
                of[mi][dc][2] *= al1; of[mi][dc][3] *= al1;
            }
#pragma unroll
            for (int nc = 0; nc < 8; nc++) {
                sf[mi][nc][0] = __expf(sf[mi][nc][0] - mn0);
                sf[mi][nc][1] = __expf(sf[mi][nc][1] - mn0);
                sf[mi][nc][2] = __expf(sf[mi][nc][2] - mn1);
                sf[mi][nc][3] = __expf(sf[mi][nc][3] - mn1);
                lrow[mi][0] += sf[mi][nc][0] + sf[mi][nc][1];
                lrow[mi][1] += sf[mi][nc][2] + sf[mi][nc][3];
            }
            mrow[mi][0] = mn0; mrow[mi][1] = mn1;

            // write P tile (warp-private rows)
            float* pw = Ps + (w * 32 + mi * 16) * ATT_LD;
#pragma unroll
            for (int nc = 0; nc < 8; nc++) {
                pw[g * ATT_LD + nc * 8 + 2 * tig]           = sf[mi][nc][0];
                pw[g * ATT_LD + nc * 8 + 2 * tig + 1]       = sf[mi][nc][1];
                pw[(g + 8) * ATT_LD + nc * 8 + 2 * tig]     = sf[mi][nc][2];
                pw[(g + 8) * ATT_LD + nc * 8 + 2 * tig + 1] = sf[mi][nc][3];
            }
        }
        __syncwarp();

        // O += P @ V : two P tiles share every V fragment (x4 = 2 d-tiles)
#pragma unroll
        for (int kc = 0; kc < 8; kc++) {
            uint32_t pf[2][4];
            ldsm_x4(pf[0], Ps_u +
                (uint32_t)((w * 32 + a_lrow) * ATT_LD + kc * 8 + a_koff) * 4);
            ldsm_x4(pf[1], Ps_u +
                (uint32_t)((w * 32 + 16 + a_lrow) * ATT_LD + kc * 8 + a_koff) * 4);
#pragma unroll
            for (int dc = 0; dc < 8; dc += 2) {
                uint32_t bf[4];
                ldsm_x4(bf, Vt_u +
                    (uint32_t)(((dc + b_tile) * 8 + b_lrow) * ATT_LD + kc * 8 + b_koff) * 4);
                mma_tf32(of[0][dc],     pf[0], bf);
                mma_tf32(of[1][dc],     pf[1], bf);
                mma_tf32(of[0][dc + 1], pf[0], bf + 2);
                mma_tf32(of[1][dc + 1], pf[1], bf + 2);
            }
        }
        __syncwarp();
    }

    // finalize
#pragma unroll
    for (int mi = 0; mi < 2; mi++) {
        float l0 = lrow[mi][0], l1 = lrow[mi][1];
        l0 += __shfl_xor_sync(0xFFFFFFFF, l0, 1);
        l0 += __shfl_xor_sync(0xFFFFFFFF, l0, 2);
        l1 += __shfl_xor_sync(0xFFFFFFFF, l1, 1);
        l1 += __shfl_xor_sync(0xFFFFFFFF, l1, 2);
        const float inv0 = 1.f / l0, inv1 = 1.f / l1;

        float* yp = y + ((size_t)b * T_LEN + q0 + w * 32 + mi * 16) * C_DIM + h * HDIM;
#pragma unroll
        for (int dc = 0; dc < 8; dc++) {
            const int col = dc * 8 + 2 * tig;
            *(float2*)(yp + (size_t)g * C_DIM + col) =
                make_float2(of[mi][dc][0] * inv0, of[mi][dc][1] * inv0);
            *(float2*)(yp + (size_t)(g + 8) * C_DIM + col) =
                make_float2(of[mi][dc][2] * inv1, of[mi][dc][3] * inv1);
        }
    }
}

// -----------------------------------------------------------------------------
extern "C" void kernel_launch(void* const* d_in, const int* in_sizes, int n_in,
                              void* d_out, int out_size) {
    const float* x     = (const float*)d_in[0];
    const float* ln1_g = (const float*)d_in[1];
    const float* ln1_b = (const float*)d_in[2];
    const float* ln2_g = (const float*)d_in[3];
    const float* ln2_b = (const float*)d_in[4];
    const float* ln3_g = (const float*)d_in[5];
    const float* ln3_b = (const float*)d_in[6];
    const float* wq = (const float*)d_in[7];   const float* bq = (const float*)d_in[8];
    const float* wk = (const float*)d_in[9];   const float* bk = (const float*)d_in[10];
    const float* wv = (const float*)d_in[11];  const float* bv = (const float*)d_in[12];
    const float* wo = (const float*)d_in[13];  const float* bo = (const float*)d_in[14];
    const float* w1 = (const float*)d_in[15];  const float* b1 = (const float*)d_in[16];
    const float* w2 = (const float*)d_in[17];  const float* b2 = (const float*)d_in[18];
    const float* wd = (const float*)d_in[19];  const float* bd = (const float*)d_in[20];
    const float* wu = (const float*)d_in[21];  const float* bu = (const float*)d_in[22];
    float* out = (float*)d_out;

    float *h, *q, *k, *v, *y, *hidden, *m, *ff, *mlp, *n3, *ad1;
    cudaGetSymbolAddress((void**)&h,      g_h);
    cudaGetSymbolAddress((void**)&q,      g_q);
    cudaGetSymbolAddress((void**)&k,      g_k);
    cudaGetSymbolAddress((void**)&v,      g_v);
    cudaGetSymbolAddress((void**)&y,      g_y);
    cudaGetSymbolAddress((void**)&hidden, g_hidden);
    cudaGetSymbolAddress((void**)&m,      g_m);
    cudaGetSymbolAddress((void**)&ff,     g_ff);
    cudaGetSymbolAddress((void**)&mlp,    g_mlp);
    cudaGetSymbolAddress((void**)&n3,     g_n3);
    cudaGetSymbolAddress((void**)&ad1,    g_ad1);

    cudaFuncSetAttribute(qkv_gemm, cudaFuncAttributeMaxDynamicSharedMemorySize, gemm_smem<4>());
    cudaFuncSetAttribute(tc_gemm<1, 0, 4>, cudaFuncAttributeMaxDynamicSharedMemorySize, gemm_smem<4>());
    cudaFuncSetAttribute(tc_gemm<0, 1, 2>, cudaFuncAttributeMaxDynamicSharedMemorySize, gemm_smem<2>());
    cudaFuncSetAttribute(tc_gemm<0, 0, 2>, cudaFuncAttributeMaxDynamicSharedMemorySize, gemm_smem<2>());
    cudaFuncSetAttribute(tc_gemm<0, 2, 2>, cudaFuncAttributeMaxDynamicSharedMemorySize, gemm_smem<2>());
    cudaFuncSetAttribute(adapter_down, cudaFuncAttributeMaxDynamicSharedMemorySize, AD_SMEM);
    cudaFuncSetAttribute(attn_mma, cudaFuncAttributeMaxDynamicSharedMemorySize, ATT_SMEM);

    // LN1(x), LN3(x)
    ln_kernel<<<M_ROWS / 8, 256>>>(x, ln1_g, ln1_b, h);
    ln_kernel<<<M_ROWS / 8, 256>>>(x, ln3_g, ln3_b, n3);

    // fused QKV projection
    qkv_gemm<<<dim3(24, 32), 256, gemm_smem<4>()>>>(h, wq, wk, wv, bq, bk, bv, q, k, v);

    // Causal attention (tensor cores, 128-query tiles)
    attn_mma<<<dim3(4 * NHEAD, T_LEN / ATT_QT), 128, ATT_SMEM>>>(q, k, v, y);

    // Output projection + residual -> hidden
    tc_gemm<0, 1, 2><<<dim3(8, 64), 256, gemm_smem<2>()>>>(y, wo, bo, x, nullptr, hidden, C_DIM, C_DIM);

    // adapter-down on ln3(x) (tensor cores; independent of attention path)
    adapter_down<<<32, 256, AD_SMEM>>>(n3, wd, bd, ad1, C_DIM);

    // MLP on ln2(hidden)
    ln_kernel<<<M_ROWS / 8, 256>>>(hidden, ln2_g, ln2_b, m);
    tc_gemm<1, 0, 4><<<dim3(32, 32), 256, gemm_smem<4>()>>>(m, w1, b1, nullptr, nullptr, ff, FF_DIM, C_DIM);
    tc_gemm<0, 0, 2><<<dim3(8, 64), 256, gemm_smem<2>()>>>(ff, w2, b2, nullptr, nullptr, mlp, C_DIM, FF_DIM);

    // adapter-up + final combine: out = (ad1@wu + bu) + 2*hidden + mlp
    tc_gemm<0, 2, 2><<<dim3(8, 64), 256, gemm_smem<2>()>>>(ad1, wu, bu, hidden, mlp, out, C_DIM, A_DIM);
}